// round 7
// baseline (speedup 1.0000x reference)
#include <cuda_runtime.h>
#include <cuda_bf16.h>
#include <cstdint>

#define BOOKS 8
#define NROWS 1024
#define INFEAT 2048
#define OUTF 4096
#define LW 256
#define WORDS 256

// Scratch (device globals; no runtime allocation allowed)
__device__ __nv_bfloat16 g_xh[BOOKS * NROWS * LW];
__device__ __nv_bfloat16 g_xl[BOOKS * NROWS * LW];
__device__ __nv_bfloat16 g_sh[BOOKS * NROWS * LW];
__device__ __nv_bfloat16 g_sl[BOOKS * NROWS * LW];
__device__ __nv_bfloat16 g_wh[BOOKS * OUTF * LW];
__device__ __nv_bfloat16 g_wl[BOOKS * OUTF * LW];
__device__ float g_winv[BOOKS * OUTF];

// ===========================================================================
// helpers
// ===========================================================================
__device__ __forceinline__ uint32_t smem_u32(const void* p) {
    uint32_t a;
    asm("{ .reg .u64 t; cvta.to.shared.u64 t, %1; cvt.u32.u64 %0, t; }" : "=r"(a) : "l"(p));
    return a;
}
__device__ __forceinline__ void cp16(uint32_t dst, const void* src) {
    asm volatile("cp.async.cg.shared.global [%0], [%1], 16;" :: "r"(dst), "l"(src));
}
__device__ __forceinline__ void cp_commit() { asm volatile("cp.async.commit_group;"); }
__device__ __forceinline__ void cp_wait1()  { asm volatile("cp.async.wait_group 1;"); }
__device__ __forceinline__ void cp_wait0()  { asm volatile("cp.async.wait_group 0;"); }

__device__ __forceinline__ void ldm4(uint32_t* r, uint32_t addr) {
    asm volatile("ldmatrix.sync.aligned.m8n8.x4.shared.b16 {%0,%1,%2,%3}, [%4];"
                 : "=r"(r[0]), "=r"(r[1]), "=r"(r[2]), "=r"(r[3]) : "r"(addr));
}
__device__ __forceinline__ void mma16816(float* d, const uint32_t* a, const uint32_t* b) {
    asm volatile(
        "mma.sync.aligned.m16n8k16.row.col.f32.bf16.bf16.f32 "
        "{%0,%1,%2,%3}, {%4,%5,%6,%7}, {%8,%9}, {%0,%1,%2,%3};"
        : "+f"(d[0]), "+f"(d[1]), "+f"(d[2]), "+f"(d[3])
        : "r"(a[0]), "r"(a[1]), "r"(a[2]), "r"(a[3]), "r"(b[0]), "r"(b[1]));
}
__device__ __forceinline__ void split_bf16(float v, __nv_bfloat16& h, __nv_bfloat16& l) {
    h = __float2bfloat16(v);
    l = __float2bfloat16(v - __bfloat162float(h));
}

// ---------------------------------------------------------------------------
// wnorm: inverse norms of weight rows. 8 warps/block, 1 row/warp.
// ---------------------------------------------------------------------------
__global__ void wnorm_kernel(const float* __restrict__ weight) {
    int row  = blockIdx.x * 8 + (threadIdx.x >> 5);
    int lane = threadIdx.x & 31;
    const float* w = weight + (size_t)row * LW;
    float ss = 0.f;
#pragma unroll
    for (int j = 0; j < 8; j++) { float v = w[lane + 32 * j]; ss += v * v; }
#pragma unroll
    for (int o = 16; o > 0; o >>= 1) ss += __shfl_xor_sync(0xffffffffu, ss, o);
    if (lane == 0) g_winv[row] = 1.0f / fmaxf(sqrtf(ss), 1e-12f);
}

// ---------------------------------------------------------------------------
// wsplit: elementwise hi/lo bf16 split of weight. 4 elems/thread.
// ---------------------------------------------------------------------------
__global__ void wsplit_kernel(const float* __restrict__ weight) {
    size_t i = (size_t)blockIdx.x * 256 + threadIdx.x;   // float4 index
    float4 v = ((const float4*)weight)[i];
    __nv_bfloat16 h0, h1, h2, h3, l0, l1, l2, l3;
    split_bf16(v.x, h0, l0); split_bf16(v.y, h1, l1);
    split_bf16(v.z, h2, l2); split_bf16(v.w, h3, l3);
    ((__nv_bfloat162*)g_wh)[2 * i]     = __nv_bfloat162(h0, h1);
    ((__nv_bfloat162*)g_wh)[2 * i + 1] = __nv_bfloat162(h2, h3);
    ((__nv_bfloat162*)g_wl)[2 * i]     = __nv_bfloat162(l0, l1);
    ((__nv_bfloat162*)g_wl)[2 * i + 1] = __nv_bfloat162(l2, l3);
}

// ---------------------------------------------------------------------------
// bookA: xn, softmax(x@mlp)->xc, s=cb@xc, sn; writes hi/lo bf16 planes.
// Inner loops vectorized (float4 smem reads) -> FFMA-bound.
// ---------------------------------------------------------------------------
__global__ void bookA_kernel(const float* __restrict__ input,
                             const float* __restrict__ mlp,
                             const float* __restrict__ cb,
                             float* __restrict__ out_xc) {
    extern __shared__ float sm[];
    float* xc_s = sm;
    float* cb_s = sm + 4096;
    float* s_s  = sm + 12544;
    float* x_s  = sm + 16656;
    __shared__ float rinv[16], rmax[16], rsum[16];

    int b = blockIdx.y, n0 = blockIdx.x * 16;
    int t = threadIdx.x, wid = t >> 5, lane = t & 31;

#pragma unroll
    for (int i = 0; i < 16; i++)
        x_s[i * 256 + t] = input[(size_t)(n0 + i) * INFEAT + b * 256 + t];
    __syncthreads();

    for (int i = wid; i < 16; i += 8) {
        float ss = 0.f;
#pragma unroll
        for (int j = 0; j < 8; j++) { float v = x_s[i * 256 + lane + 32 * j]; ss += v * v; }
#pragma unroll
        for (int o = 16; o > 0; o >>= 1) ss += __shfl_xor_sync(0xffffffffu, ss, o);
        if (!lane) rinv[i] = 1.0f / fmaxf(sqrtf(ss), 1e-12f);
    }
    __syncthreads();
#pragma unroll
    for (int i = 0; i < 16; i++) {
        float v = x_s[i * 256 + t] * rinv[i];
        __nv_bfloat16 h, l; split_bf16(v, h, l);
        size_t idx = (size_t)((b << 10) + (n0 + i)) * 256 + t;
        g_xh[idx] = h; g_xl[idx] = l;
    }

    float acc[16];
#pragma unroll
    for (int i = 0; i < 16; i++) acc[i] = 0.f;
    const float* mp = mlp + b * 65536 + t;
#pragma unroll 2
    for (int d = 0; d < 256; d += 4) {
        float m0 = __ldg(mp + (d + 0) * 256);
        float m1 = __ldg(mp + (d + 1) * 256);
        float m2 = __ldg(mp + (d + 2) * 256);
        float m3 = __ldg(mp + (d + 3) * 256);
#pragma unroll
        for (int i = 0; i < 16; i++) {
            float4 xv = *(const float4*)(x_s + i * 256 + d);
            acc[i] += xv.x * m0 + xv.y * m1 + xv.z * m2 + xv.w * m3;
        }
    }
    __syncthreads();
#pragma unroll
    for (int i = 0; i < 16; i++) xc_s[i * 256 + t] = acc[i];
    __syncthreads();

    for (int i = wid; i < 16; i += 8) {
        float m = -3.4e38f;
#pragma unroll
        for (int j = 0; j < 8; j++) m = fmaxf(m, xc_s[i * 256 + lane + 32 * j]);
#pragma unroll
        for (int o = 16; o > 0; o >>= 1) m = fmaxf(m, __shfl_xor_sync(0xffffffffu, m, o));
        float se = 0.f;
#pragma unroll
        for (int j = 0; j < 8; j++) se += expf(xc_s[i * 256 + lane + 32 * j] - m);
#pragma unroll
        for (int o = 16; o > 0; o >>= 1) se += __shfl_xor_sync(0xffffffffu, se, o);
        if (!lane) { rmax[i] = m; rsum[i] = 1.0f / se; }
    }
    __syncthreads();
#pragma unroll
    for (int i = 0; i < 16; i++) {
        float v = expf(acc[i] - rmax[i]) * rsum[i];
        xc_s[i * 256 + t] = v;
        out_xc[(size_t)(n0 + i) * (BOOKS * WORDS) + b * 256 + t] = v;
    }

    int i0 = t >> 5, dl = t & 31;
    const float* cbb = cb + b * 65536;
    for (int c = 0; c < 8; c++) {
        __syncthreads();
#pragma unroll
        for (int d2 = 0; d2 < 32; d2++)
            cb_s[t * 33 + d2] = cbb[(c * 32 + d2) * 256 + t];
        __syncthreads();
        float s0 = 0.f, s1 = 0.f;
#pragma unroll 2
        for (int w = 0; w < 256; w += 4) {
            float c0 = cb_s[(w + 0) * 33 + dl];
            float c1 = cb_s[(w + 1) * 33 + dl];
            float c2 = cb_s[(w + 2) * 33 + dl];
            float c3 = cb_s[(w + 3) * 33 + dl];
            float4 a = *(const float4*)(xc_s + i0 * 256 + w);
            float4 d = *(const float4*)(xc_s + (i0 + 8) * 256 + w);
            s0 += a.x * c0 + a.y * c1 + a.z * c2 + a.w * c3;
            s1 += d.x * c0 + d.y * c1 + d.z * c2 + d.w * c3;
        }
        s_s[i0 * 257 + c * 32 + dl]       = s0;
        s_s[(i0 + 8) * 257 + c * 32 + dl] = s1;
    }
    __syncthreads();

    for (int i = wid; i < 16; i += 8) {
        float ss = 0.f;
#pragma unroll
        for (int j = 0; j < 8; j++) { float v = s_s[i * 257 + lane + 32 * j]; ss += v * v; }
#pragma unroll
        for (int o = 16; o > 0; o >>= 1) ss += __shfl_xor_sync(0xffffffffu, ss, o);
        if (!lane) rinv[i] = 1.0f / fmaxf(sqrtf(ss), 1e-12f);
    }
    __syncthreads();
#pragma unroll
    for (int i = 0; i < 16; i++) {
        float v = s_s[i * 257 + t] * rinv[i];
        __nv_bfloat16 h, l; split_bf16(v, h, l);
        size_t idx = (size_t)((b << 10) + (n0 + i)) * 256 + t;
        g_sh[idx] = h; g_sl[idx] = l;
    }
}

// ---------------------------------------------------------------------------
// Dual GEMM via mma.sync bf16 split-2. 512 threads / 16 warps.
// Block 128(n) x 128(o), BK=32 fp32-k per stage, double buffered.
// Stage layout (bf16, rows padded to 40 elems = 80B):
//   xh xl sh sl wh wl  each [128][40] = 10240 B -> stage 61440 B, x2 = 122880 B
// Warp grid 2(m) x 8(o) -> warp tile 64 x 16; mma m16n8k16.
// acc1 = xn@w, acc2 = sn@w share B fragments; mt-outer fragment staging.
// ---------------------------------------------------------------------------
#define TILE_B 10240
#define STAGE_B 61440

__global__ void __launch_bounds__(512, 1)
gemm_mma(const int* __restrict__ label,
         float* __restrict__ out1,
         float* __restrict__ out2) {
    extern __shared__ char smc[];
    __shared__ float winv_s[128];
    uint32_t sb = smem_u32(smc);
    int t = threadIdx.x, wid = t >> 5, lane = t & 31;
    int b = blockIdx.z, n0 = blockIdx.y * 128, o0 = blockIdx.x * 128;

    if (t < 128) winv_s[t] = g_winv[b * OUTF + o0 + t];

    const __nv_bfloat16* pxh = g_xh + (size_t)((b << 10) + n0) * 256;
    const __nv_bfloat16* pxl = g_xl + (size_t)((b << 10) + n0) * 256;
    const __nv_bfloat16* psh = g_sh + (size_t)((b << 10) + n0) * 256;
    const __nv_bfloat16* psl = g_sl + (size_t)((b << 10) + n0) * 256;
    const __nv_bfloat16* pwh = g_wh + ((size_t)b * OUTF + o0) * 256;
    const __nv_bfloat16* pwl = g_wl + ((size_t)b * OUTF + o0) * 256;

    int lrow = t >> 2, lseg = t & 3;          // 512 threads cover 128 rows x 4 segs
    uint32_t cpo = (uint32_t)(lrow * 80 + lseg * 16);
    int ge = lrow * 256 + lseg * 8;

#define LOAD_STAGE(chunk, buf)                                              \
    {                                                                       \
        uint32_t base_ = sb + (uint32_t)(buf) * STAGE_B;                    \
        int g_ = ge + (chunk) * 32;                                         \
        cp16(base_ + cpo,              pxh + g_);                           \
        cp16(base_ + TILE_B + cpo,     pxl + g_);                           \
        cp16(base_ + 2 * TILE_B + cpo, psh + g_);                           \
        cp16(base_ + 3 * TILE_B + cpo, psl + g_);                           \
        cp16(base_ + 4 * TILE_B + cpo, pwh + g_);                           \
        cp16(base_ + 5 * TILE_B + cpo, pwl + g_);                           \
        cp_commit();                                                        \
    }

    int wm = wid & 1, wo = wid >> 1;
    int m0 = wm * 64, ow0 = wo * 16;

    float acc1[4][2][4], acc2[4][2][4];
#pragma unroll
    for (int mt = 0; mt < 4; mt++)
#pragma unroll
        for (int ot = 0; ot < 2; ot++)
#pragma unroll
            for (int q = 0; q < 4; q++) { acc1[mt][ot][q] = 0.f; acc2[mt][ot][q] = 0.f; }

    uint32_t a_row = (uint32_t)(m0 + (lane & 15));
    uint32_t b_row = (uint32_t)(ow0 + (lane & 7) + ((lane >> 4) & 1) * 8);

    LOAD_STAGE(0, 0)
    LOAD_STAGE(1, 1)

    for (int i = 0; i < 8; i++) {
        if (i < 7) cp_wait1(); else cp_wait0();
        __syncthreads();
        uint32_t base = sb + (uint32_t)(i & 1) * STAGE_B;

#pragma unroll
        for (int kk = 0; kk < 32; kk += 16) {
            uint32_t a_addr = base + a_row * 80 + (uint32_t)((kk + ((lane >> 4) & 1) * 8) * 2);
            uint32_t b_addr = base + b_row * 80 + (uint32_t)((kk + ((lane >> 3) & 1) * 8) * 2);

            uint32_t fwh[4], fwl[4];
            ldm4(fwh, b_addr + 4 * TILE_B);
            ldm4(fwl, b_addr + 5 * TILE_B);

#pragma unroll
            for (int mt = 0; mt < 4; mt++) {
                uint32_t ao = a_addr + (uint32_t)(mt * 16 * 80);
                uint32_t fxh[4], fxl[4], fsh[4], fsl[4];
                ldm4(fxh, ao);
                ldm4(fxl, ao + TILE_B);
                ldm4(fsh, ao + 2 * TILE_B);
                ldm4(fsl, ao + 3 * TILE_B);
#pragma unroll
                for (int ot = 0; ot < 2; ot++) {
                    const uint32_t* bh = &fwh[ot * 2];
                    const uint32_t* bl = &fwl[ot * 2];
                    mma16816(acc1[mt][ot], fxh, bh);
                    mma16816(acc2[mt][ot], fsh, bh);
                    mma16816(acc1[mt][ot], fxh, bl);
                    mma16816(acc2[mt][ot], fsh, bl);
                    mma16816(acc1[mt][ot], fxl, bh);
                    mma16816(acc2[mt][ot], fsl, bh);
                }
            }
        }
        __syncthreads();
        if (i + 2 < 8) LOAD_STAGE(i + 2, i & 1)
    }

    // ---- epilogue
#pragma unroll
    for (int mt = 0; mt < 4; mt++) {
        int r  = n0 + m0 + mt * 16 + (lane >> 2);
        int la = label[r], lb = label[r + 8];
        size_t ro  = (size_t)r * (BOOKS * OUTF) + (size_t)b * OUTF;
        size_t ro8 = ro + (size_t)8 * (BOOKS * OUTF);
#pragma unroll
        for (int ot = 0; ot < 2; ot++) {
            int oc = ow0 + ot * 8 + 2 * (lane & 3);
            int o  = o0 + oc;
            float wi0 = winv_s[oc], wi1 = winv_s[oc + 1];
            float* A = acc1[mt][ot];
            float* C = acc2[mt][ot];
            float v;
            float2 u;
            v = fminf(fmaxf(A[0] * wi0, -1.f), 1.f); if (la == o)     v -= .5f; u.x = 30.f * v;
            v = fminf(fmaxf(A[1] * wi1, -1.f), 1.f); if (la == o + 1) v -= .5f; u.y = 30.f * v;
            *(float2*)(out1 + ro + o) = u;
            v = fminf(fmaxf(A[2] * wi0, -1.f), 1.f); if (lb == o)     v -= .5f; u.x = 30.f * v;
            v = fminf(fmaxf(A[3] * wi1, -1.f), 1.f); if (lb == o + 1) v -= .5f; u.y = 30.f * v;
            *(float2*)(out1 + ro8 + o) = u;
            v = fminf(fmaxf(C[0] * wi0, -1.f), 1.f); if (la == o)     v -= .5f; u.x = 30.f * v;
            v = fminf(fmaxf(C[1] * wi1, -1.f), 1.f); if (la == o + 1) v -= .5f; u.y = 30.f * v;
            *(float2*)(out2 + ro + o) = u;
            v = fminf(fmaxf(C[2] * wi0, -1.f), 1.f); if (lb == o)     v -= .5f; u.x = 30.f * v;
            v = fminf(fmaxf(C[3] * wi1, -1.f), 1.f); if (lb == o + 1) v -= .5f; u.y = 30.f * v;
            *(float2*)(out2 + ro8 + o) = u;
        }
    }
}

// ---------------------------------------------------------------------------
extern "C" void kernel_launch(void* const* d_in, const int* in_sizes, int n_in,
                              void* d_out, int out_size) {
    const float* input  = (const float*)d_in[0];
    const int*   label  = (const int*)d_in[1];     // int32 (JAX default x64 off)
    const float* weight = (const float*)d_in[2];
    const float* mlp    = (const float*)d_in[3];
    const float* cb     = (const float*)d_in[4];

    float* out  = (float*)d_out;
    float* out1 = out;                                    // [1024][8][4096]
    float* out2 = out + (size_t)NROWS * BOOKS * OUTF;     // [1024][8][4096]
    float* out3 = out + (size_t)2 * NROWS * BOOKS * OUTF; // [1024][8][256]

    cudaFuncSetAttribute(bookA_kernel, cudaFuncAttributeMaxDynamicSharedMemorySize, 83008);
    cudaFuncSetAttribute(gemm_mma, cudaFuncAttributeMaxDynamicSharedMemorySize, 2 * STAGE_B);

    wnorm_kernel<<<(BOOKS * OUTF) / 8, 256>>>(weight);
    wsplit_kernel<<<(BOOKS * OUTF * LW) / 4 / 256, 256>>>(weight);
    bookA_kernel<<<dim3(NROWS / 16, BOOKS), 256, 83008>>>(input, mlp, cb, out3);
    gemm_mma<<<dim3(OUTF / 128, NROWS / 128, BOOKS), 512, 2 * STAGE_B>>>(label, out1, out2);
}

// round 8
// speedup vs baseline: 1.4959x; 1.4959x over previous
#include <cuda_runtime.h>
#include <cuda_bf16.h>
#include <cstdint>

#define BOOKS 8
#define NROWS 1024
#define INFEAT 2048
#define OUTF 4096
#define LW 256
#define WORDS 256

// Scratch (device globals; no runtime allocation allowed)
__device__ __nv_bfloat16 g_xh[BOOKS * NROWS * LW];
__device__ __nv_bfloat16 g_xl[BOOKS * NROWS * LW];
__device__ __nv_bfloat16 g_sh[BOOKS * NROWS * LW];
__device__ __nv_bfloat16 g_sl[BOOKS * NROWS * LW];
__device__ __nv_bfloat16 g_wh[BOOKS * OUTF * LW];
__device__ __nv_bfloat16 g_wl[BOOKS * OUTF * LW];
__device__ float g_winv[BOOKS * OUTF];

// ===========================================================================
// helpers
// ===========================================================================
__device__ __forceinline__ uint32_t smem_u32(const void* p) {
    uint32_t a;
    asm("{ .reg .u64 t; cvta.to.shared.u64 t, %1; cvt.u32.u64 %0, t; }" : "=r"(a) : "l"(p));
    return a;
}
__device__ __forceinline__ void cp16(uint32_t dst, const void* src) {
    asm volatile("cp.async.cg.shared.global [%0], [%1], 16;" :: "r"(dst), "l"(src));
}
__device__ __forceinline__ void cp_commit() { asm volatile("cp.async.commit_group;"); }
__device__ __forceinline__ void cp_wait1()  { asm volatile("cp.async.wait_group 1;"); }
__device__ __forceinline__ void cp_wait0()  { asm volatile("cp.async.wait_group 0;"); }

__device__ __forceinline__ void ldm4(uint32_t* r, uint32_t addr) {
    asm volatile("ldmatrix.sync.aligned.m8n8.x4.shared.b16 {%0,%1,%2,%3}, [%4];"
                 : "=r"(r[0]), "=r"(r[1]), "=r"(r[2]), "=r"(r[3]) : "r"(addr));
}
__device__ __forceinline__ void mma16816(float* d, const uint32_t* a, const uint32_t* b) {
    asm volatile(
        "mma.sync.aligned.m16n8k16.row.col.f32.bf16.bf16.f32 "
        "{%0,%1,%2,%3}, {%4,%5,%6,%7}, {%8,%9}, {%0,%1,%2,%3};"
        : "+f"(d[0]), "+f"(d[1]), "+f"(d[2]), "+f"(d[3])
        : "r"(a[0]), "r"(a[1]), "r"(a[2]), "r"(a[3]), "r"(b[0]), "r"(b[1]));
}
__device__ __forceinline__ void split_bf16(float v, __nv_bfloat16& h, __nv_bfloat16& l) {
    h = __float2bfloat16(v);
    l = __float2bfloat16(v - __bfloat162float(h));
}

// ---------------------------------------------------------------------------
// wnorm: inverse norms of weight rows. 8 warps/block, 1 row/warp.
// ---------------------------------------------------------------------------
__global__ void wnorm_kernel(const float* __restrict__ weight) {
    int row  = blockIdx.x * 8 + (threadIdx.x >> 5);
    int lane = threadIdx.x & 31;
    const float* w = weight + (size_t)row * LW;
    float ss = 0.f;
#pragma unroll
    for (int j = 0; j < 8; j++) { float v = w[lane + 32 * j]; ss += v * v; }
#pragma unroll
    for (int o = 16; o > 0; o >>= 1) ss += __shfl_xor_sync(0xffffffffu, ss, o);
    if (lane == 0) g_winv[row] = 1.0f / fmaxf(sqrtf(ss), 1e-12f);
}

// ---------------------------------------------------------------------------
// wsplit: elementwise hi/lo bf16 split of weight. 4 elems/thread.
// ---------------------------------------------------------------------------
__global__ void wsplit_kernel(const float* __restrict__ weight) {
    size_t i = (size_t)blockIdx.x * 256 + threadIdx.x;   // float4 index
    float4 v = ((const float4*)weight)[i];
    __nv_bfloat16 h0, h1, h2, h3, l0, l1, l2, l3;
    split_bf16(v.x, h0, l0); split_bf16(v.y, h1, l1);
    split_bf16(v.z, h2, l2); split_bf16(v.w, h3, l3);
    ((__nv_bfloat162*)g_wh)[2 * i]     = __nv_bfloat162(h0, h1);
    ((__nv_bfloat162*)g_wh)[2 * i + 1] = __nv_bfloat162(h2, h3);
    ((__nv_bfloat162*)g_wl)[2 * i]     = __nv_bfloat162(l0, l1);
    ((__nv_bfloat162*)g_wl)[2 * i + 1] = __nv_bfloat162(l2, l3);
}

// ---------------------------------------------------------------------------
// bookA: xn, softmax(x@mlp)->xc, s=cb@xc, sn; writes hi/lo bf16 planes.
// ---------------------------------------------------------------------------
__global__ void bookA_kernel(const float* __restrict__ input,
                             const float* __restrict__ mlp,
                             const float* __restrict__ cb,
                             float* __restrict__ out_xc) {
    extern __shared__ float sm[];
    float* xc_s = sm;
    float* cb_s = sm + 4096;
    float* s_s  = sm + 12544;
    float* x_s  = sm + 16656;
    __shared__ float rinv[16], rmax[16], rsum[16];

    int b = blockIdx.y, n0 = blockIdx.x * 16;
    int t = threadIdx.x, wid = t >> 5, lane = t & 31;

#pragma unroll
    for (int i = 0; i < 16; i++)
        x_s[i * 256 + t] = input[(size_t)(n0 + i) * INFEAT + b * 256 + t];
    __syncthreads();

    for (int i = wid; i < 16; i += 8) {
        float ss = 0.f;
#pragma unroll
        for (int j = 0; j < 8; j++) { float v = x_s[i * 256 + lane + 32 * j]; ss += v * v; }
#pragma unroll
        for (int o = 16; o > 0; o >>= 1) ss += __shfl_xor_sync(0xffffffffu, ss, o);
        if (!lane) rinv[i] = 1.0f / fmaxf(sqrtf(ss), 1e-12f);
    }
    __syncthreads();
#pragma unroll
    for (int i = 0; i < 16; i++) {
        float v = x_s[i * 256 + t] * rinv[i];
        __nv_bfloat16 h, l; split_bf16(v, h, l);
        size_t idx = (size_t)((b << 10) + (n0 + i)) * 256 + t;
        g_xh[idx] = h; g_xl[idx] = l;
    }

    float acc[16];
#pragma unroll
    for (int i = 0; i < 16; i++) acc[i] = 0.f;
    const float* mp = mlp + b * 65536 + t;
#pragma unroll 2
    for (int d = 0; d < 256; d += 4) {
        float m0 = __ldg(mp + (d + 0) * 256);
        float m1 = __ldg(mp + (d + 1) * 256);
        float m2 = __ldg(mp + (d + 2) * 256);
        float m3 = __ldg(mp + (d + 3) * 256);
#pragma unroll
        for (int i = 0; i < 16; i++) {
            float4 xv = *(const float4*)(x_s + i * 256 + d);
            acc[i] += xv.x * m0 + xv.y * m1 + xv.z * m2 + xv.w * m3;
        }
    }
    __syncthreads();
#pragma unroll
    for (int i = 0; i < 16; i++) xc_s[i * 256 + t] = acc[i];
    __syncthreads();

    for (int i = wid; i < 16; i += 8) {
        float m = -3.4e38f;
#pragma unroll
        for (int j = 0; j < 8; j++) m = fmaxf(m, xc_s[i * 256 + lane + 32 * j]);
#pragma unroll
        for (int o = 16; o > 0; o >>= 1) m = fmaxf(m, __shfl_xor_sync(0xffffffffu, m, o));
        float se = 0.f;
#pragma unroll
        for (int j = 0; j < 8; j++) se += expf(xc_s[i * 256 + lane + 32 * j] - m);
#pragma unroll
        for (int o = 16; o > 0; o >>= 1) se += __shfl_xor_sync(0xffffffffu, se, o);
        if (!lane) { rmax[i] = m; rsum[i] = 1.0f / se; }
    }
    __syncthreads();
#pragma unroll
    for (int i = 0; i < 16; i++) {
        float v = expf(acc[i] - rmax[i]) * rsum[i];
        xc_s[i * 256 + t] = v;
        out_xc[(size_t)(n0 + i) * (BOOKS * WORDS) + b * 256 + t] = v;
    }

    int i0 = t >> 5, dl = t & 31;
    const float* cbb = cb + b * 65536;
    for (int c = 0; c < 8; c++) {
        __syncthreads();
#pragma unroll
        for (int d2 = 0; d2 < 32; d2++)
            cb_s[t * 33 + d2] = cbb[(c * 32 + d2) * 256 + t];
        __syncthreads();
        float s0 = 0.f, s1 = 0.f;
#pragma unroll 2
        for (int w = 0; w < 256; w += 4) {
            float c0 = cb_s[(w + 0) * 33 + dl];
            float c1 = cb_s[(w + 1) * 33 + dl];
            float c2 = cb_s[(w + 2) * 33 + dl];
            float c3 = cb_s[(w + 3) * 33 + dl];
            float4 a = *(const float4*)(xc_s + i0 * 256 + w);
            float4 d = *(const float4*)(xc_s + (i0 + 8) * 256 + w);
            s0 += a.x * c0 + a.y * c1 + a.z * c2 + a.w * c3;
            s1 += d.x * c0 + d.y * c1 + d.z * c2 + d.w * c3;
        }
        s_s[i0 * 257 + c * 32 + dl]       = s0;
        s_s[(i0 + 8) * 257 + c * 32 + dl] = s1;
    }
    __syncthreads();

    for (int i = wid; i < 16; i += 8) {
        float ss = 0.f;
#pragma unroll
        for (int j = 0; j < 8; j++) { float v = s_s[i * 257 + lane + 32 * j]; ss += v * v; }
#pragma unroll
        for (int o = 16; o > 0; o >>= 1) ss += __shfl_xor_sync(0xffffffffu, ss, o);
        if (!lane) rinv[i] = 1.0f / fmaxf(sqrtf(ss), 1e-12f);
    }
    __syncthreads();
#pragma unroll
    for (int i = 0; i < 16; i++) {
        float v = s_s[i * 257 + t] * rinv[i];
        __nv_bfloat16 h, l; split_bf16(v, h, l);
        size_t idx = (size_t)((b << 10) + (n0 + i)) * 256 + t;
        g_sh[idx] = h; g_sl[idx] = l;
    }
}

// ---------------------------------------------------------------------------
// Dual GEMM via mma.sync bf16 split-2, warp-specialized by output.
// 512 threads / 16 warps. Block 128(n) x 128(o), BK=32 fp32-k, double buffered.
// Warps 0-7:  out1 = xn@w   (read xh/xl + wh/wl)
// Warps 8-15: out2 = sn@w   (read sh/sl + wh/wl)
// Each group: 2(m) x 4(o) warp grid -> warp tile 64 x 32 (same as R4).
// Stage layout (bf16 rows padded to 40 elems = 80B):
//   xh xl sh sl wh wl  each [128][40] = 10240 B -> stage 61440 B, x2 = 122880 B
// ---------------------------------------------------------------------------
#define TILE_B 10240
#define STAGE_B 61440

__global__ void __launch_bounds__(512, 1)
gemm_mma(const int* __restrict__ label,
         float* __restrict__ out1,
         float* __restrict__ out2) {
    extern __shared__ char smc[];
    __shared__ float winv_s[128];
    uint32_t sb = smem_u32(smc);
    int t = threadIdx.x, wid = t >> 5, lane = t & 31;
    int b = blockIdx.z, n0 = blockIdx.y * 128, o0 = blockIdx.x * 128;

    if (t < 128) winv_s[t] = g_winv[b * OUTF + o0 + t];

    const __nv_bfloat16* pxh = g_xh + (size_t)((b << 10) + n0) * 256;
    const __nv_bfloat16* pxl = g_xl + (size_t)((b << 10) + n0) * 256;
    const __nv_bfloat16* psh = g_sh + (size_t)((b << 10) + n0) * 256;
    const __nv_bfloat16* psl = g_sl + (size_t)((b << 10) + n0) * 256;
    const __nv_bfloat16* pwh = g_wh + ((size_t)b * OUTF + o0) * 256;
    const __nv_bfloat16* pwl = g_wl + ((size_t)b * OUTF + o0) * 256;

    int lrow = t >> 2, lseg = t & 3;          // 512 threads cover 128 rows x 4 segs
    uint32_t cpo = (uint32_t)(lrow * 80 + lseg * 16);
    int ge = lrow * 256 + lseg * 8;

#define LOAD_STAGE(chunk, buf)                                              \
    {                                                                       \
        uint32_t base_ = sb + (uint32_t)(buf) * STAGE_B;                    \
        int g_ = ge + (chunk) * 32;                                         \
        cp16(base_ + cpo,              pxh + g_);                           \
        cp16(base_ + TILE_B + cpo,     pxl + g_);                           \
        cp16(base_ + 2 * TILE_B + cpo, psh + g_);                           \
        cp16(base_ + 3 * TILE_B + cpo, psl + g_);                           \
        cp16(base_ + 4 * TILE_B + cpo, pwh + g_);                           \
        cp16(base_ + 5 * TILE_B + cpo, pwl + g_);                           \
        cp_commit();                                                        \
    }

    int wg  = wid >> 3;            // 0: x->out1, 1: s->out2
    int wl8 = wid & 7;
    int wm = wl8 & 1, wo = wl8 >> 1;
    int m0 = wm * 64, ow0 = wo * 32;
    uint32_t aoff_h = (uint32_t)(wg * 2) * TILE_B;       // xh or sh plane
    uint32_t aoff_l = aoff_h + TILE_B;                   // xl or sl plane

    float acc[4][4][4];
#pragma unroll
    for (int mt = 0; mt < 4; mt++)
#pragma unroll
        for (int ot = 0; ot < 4; ot++)
#pragma unroll
            for (int q = 0; q < 4; q++) acc[mt][ot][q] = 0.f;

    // ldmatrix lane-address components (same scheme as validated R4)
    uint32_t a_row = (uint32_t)(m0 + (lane & 7) + ((lane >> 3) & 1) * 8);
    uint32_t b_row = (uint32_t)(ow0 + (lane & 7) + ((lane >> 4) & 1) * 8);

    LOAD_STAGE(0, 0)
    LOAD_STAGE(1, 1)

    for (int i = 0; i < 8; i++) {
        if (i < 7) cp_wait1(); else cp_wait0();
        __syncthreads();
        uint32_t base = sb + (uint32_t)(i & 1) * STAGE_B;

#pragma unroll
        for (int kk = 0; kk < 32; kk += 16) {
            uint32_t a_addr = base + a_row * 80 + (uint32_t)((kk + ((lane >> 4) & 1) * 8) * 2);
            uint32_t b_addr = base + b_row * 80 + (uint32_t)((kk + ((lane >> 3) & 1) * 8) * 2);

            uint32_t fwh[2][4], fwl[2][4];   // pair p covers ot=2p, 2p+1
#pragma unroll
            for (int p = 0; p < 2; p++) {
                uint32_t bo = b_addr + (uint32_t)(p * 16 * 80);
                ldm4(fwh[p], bo + 4 * TILE_B);
                ldm4(fwl[p], bo + 5 * TILE_B);
            }
#pragma unroll
            for (int mt = 0; mt < 4; mt++) {
                uint32_t ao = a_addr + (uint32_t)(mt * 16 * 80);
                uint32_t fah[4], fal[4];
                ldm4(fah, ao + aoff_h);
                ldm4(fal, ao + aoff_l);
#pragma unroll
                for (int ot = 0; ot < 4; ot++) {
                    const uint32_t* bh = &fwh[ot >> 1][(ot & 1) * 2];
                    const uint32_t* bl = &fwl[ot >> 1][(ot & 1) * 2];
                    mma16816(acc[mt][ot], fah, bh);
                    mma16816(acc[mt][ot], fah, bl);
                    mma16816(acc[mt][ot], fal, bh);
                }
            }
        }
        __syncthreads();
        if (i + 2 < 8) LOAD_STAGE(i + 2, i & 1)
    }

    // ---- epilogue: each warp group writes its own output
    float* op = wg ? out2 : out1;
#pragma unroll
    for (int mt = 0; mt < 4; mt++) {
        int r  = n0 + m0 + mt * 16 + (lane >> 2);
        int la = label[r], lb = label[r + 8];
        size_t ro  = (size_t)r * (BOOKS * OUTF) + (size_t)b * OUTF;
        size_t ro8 = ro + (size_t)8 * (BOOKS * OUTF);
#pragma unroll
        for (int ot = 0; ot < 4; ot++) {
            int oc = ow0 + ot * 8 + 2 * (lane & 3);
            int o  = o0 + oc;
            float wi0 = winv_s[oc], wi1 = winv_s[oc + 1];
            float* A = acc[mt][ot];
            float v;
            float2 u;
            v = fminf(fmaxf(A[0] * wi0, -1.f), 1.f); if (la == o)     v -= .5f; u.x = 30.f * v;
            v = fminf(fmaxf(A[1] * wi1, -1.f), 1.f); if (la == o + 1) v -= .5f; u.y = 30.f * v;
            *(float2*)(op + ro + o) = u;
            v = fminf(fmaxf(A[2] * wi0, -1.f), 1.f); if (lb == o)     v -= .5f; u.x = 30.f * v;
            v = fminf(fmaxf(A[3] * wi1, -1.f), 1.f); if (lb == o + 1) v -= .5f; u.y = 30.f * v;
            *(float2*)(op + ro8 + o) = u;
        }
    }
}

// ---------------------------------------------------------------------------
extern "C" void kernel_launch(void* const* d_in, const int* in_sizes, int n_in,
                              void* d_out, int out_size) {
    const float* input  = (const float*)d_in[0];
    const int*   label  = (const int*)d_in[1];     // int32 (JAX default x64 off)
    const float* weight = (const float*)d_in[2];
    const float* mlp    = (const float*)d_in[3];
    const float* cb     = (const float*)d_in[4];

    float* out  = (float*)d_out;
    float* out1 = out;                                    // [1024][8][4096]
    float* out2 = out + (size_t)NROWS * BOOKS * OUTF;     // [1024][8][4096]
    float* out3 = out + (size_t)2 * NROWS * BOOKS * OUTF; // [1024][8][256]

    cudaFuncSetAttribute(bookA_kernel, cudaFuncAttributeMaxDynamicSharedMemorySize, 83008);
    cudaFuncSetAttribute(gemm_mma, cudaFuncAttributeMaxDynamicSharedMemorySize, 2 * STAGE_B);

    wnorm_kernel<<<(BOOKS * OUTF) / 8, 256>>>(weight);
    wsplit_kernel<<<(BOOKS * OUTF * LW) / 4 / 256, 256>>>(weight);
    bookA_kernel<<<dim3(NROWS / 16, BOOKS), 256, 83008>>>(input, mlp, cb, out3);
    gemm_mma<<<dim3(OUTF / 128, NROWS / 128, BOOKS), 512, 2 * STAGE_B>>>(label, out1, out2);
}

// round 9
// speedup vs baseline: 1.5423x; 1.0310x over previous
#include <cuda_runtime.h>
#include <cuda_bf16.h>
#include <cstdint>

#define BOOKS 8
#define NROWS 1024
#define INFEAT 2048
#define OUTF 4096
#define LW 256
#define WORDS 256

// Scratch (device globals; no runtime allocation allowed)
__device__ __nv_bfloat16 g_xh[BOOKS * NROWS * LW];
__device__ __nv_bfloat16 g_xl[BOOKS * NROWS * LW];
__device__ __nv_bfloat16 g_sh[BOOKS * NROWS * LW];
__device__ __nv_bfloat16 g_sl[BOOKS * NROWS * LW];
__device__ __nv_bfloat16 g_wh[BOOKS * OUTF * LW];
__device__ __nv_bfloat16 g_wl[BOOKS * OUTF * LW];
__device__ float g_winv[BOOKS * OUTF];

// ===========================================================================
// helpers
// ===========================================================================
__device__ __forceinline__ uint32_t smem_u32(const void* p) {
    uint32_t a;
    asm("{ .reg .u64 t; cvta.to.shared.u64 t, %1; cvt.u32.u64 %0, t; }" : "=r"(a) : "l"(p));
    return a;
}
__device__ __forceinline__ void cp16(uint32_t dst, const void* src) {
    asm volatile("cp.async.cg.shared.global [%0], [%1], 16;" :: "r"(dst), "l"(src));
}
__device__ __forceinline__ void cp_commit() { asm volatile("cp.async.commit_group;"); }
__device__ __forceinline__ void cp_wait1()  { asm volatile("cp.async.wait_group 1;"); }
__device__ __forceinline__ void cp_wait0()  { asm volatile("cp.async.wait_group 0;"); }

__device__ __forceinline__ void ldm4(uint32_t* r, uint32_t addr) {
    asm volatile("ldmatrix.sync.aligned.m8n8.x4.shared.b16 {%0,%1,%2,%3}, [%4];"
                 : "=r"(r[0]), "=r"(r[1]), "=r"(r[2]), "=r"(r[3]) : "r"(addr));
}
__device__ __forceinline__ void mma16816(float* d, const uint32_t* a, const uint32_t* b) {
    asm volatile(
        "mma.sync.aligned.m16n8k16.row.col.f32.bf16.bf16.f32 "
        "{%0,%1,%2,%3}, {%4,%5,%6,%7}, {%8,%9}, {%0,%1,%2,%3};"
        : "+f"(d[0]), "+f"(d[1]), "+f"(d[2]), "+f"(d[3])
        : "r"(a[0]), "r"(a[1]), "r"(a[2]), "r"(a[3]), "r"(b[0]), "r"(b[1]));
}
__device__ __forceinline__ void split_bf16(float v, __nv_bfloat16& h, __nv_bfloat16& l) {
    h = __float2bfloat16(v);
    l = __float2bfloat16(v - __bfloat162float(h));
}

// ---------------------------------------------------------------------------
// wprep: winv + hi/lo split of weight, single pass. 1 warp per row.
// ---------------------------------------------------------------------------
__global__ void wprep_kernel(const float* __restrict__ weight) {
    int row  = blockIdx.x * 8 + (threadIdx.x >> 5);
    int lane = threadIdx.x & 31;
    const float4* w4 = (const float4*)(weight + (size_t)row * LW);
    float ss = 0.f;
    float4 v[2];
#pragma unroll
    for (int j = 0; j < 2; j++) {
        v[j] = w4[lane + 32 * j];
        ss += v[j].x * v[j].x + v[j].y * v[j].y + v[j].z * v[j].z + v[j].w * v[j].w;
    }
#pragma unroll
    for (int o = 16; o > 0; o >>= 1) ss += __shfl_xor_sync(0xffffffffu, ss, o);
    if (lane == 0) g_winv[row] = 1.0f / fmaxf(sqrtf(ss), 1e-12f);
#pragma unroll
    for (int j = 0; j < 2; j++) {
        __nv_bfloat16 h0, h1, h2, h3, l0, l1, l2, l3;
        split_bf16(v[j].x, h0, l0); split_bf16(v[j].y, h1, l1);
        split_bf16(v[j].z, h2, l2); split_bf16(v[j].w, h3, l3);
        size_t i2 = (size_t)row * (LW / 2) + (lane + 32 * j) * 2;
        ((__nv_bfloat162*)g_wh)[i2]     = __nv_bfloat162(h0, h1);
        ((__nv_bfloat162*)g_wh)[i2 + 1] = __nv_bfloat162(h2, h3);
        ((__nv_bfloat162*)g_wl)[i2]     = __nv_bfloat162(l0, l1);
        ((__nv_bfloat162*)g_wl)[i2 + 1] = __nv_bfloat162(l2, l3);
    }
}

// ---------------------------------------------------------------------------
// bookA: xn, softmax(x@mlp)->xc, s=cb@xc, sn; writes hi/lo bf16 planes.
// ---------------------------------------------------------------------------
__global__ void bookA_kernel(const float* __restrict__ input,
                             const float* __restrict__ mlp,
                             const float* __restrict__ cb,
                             float* __restrict__ out_xc) {
    extern __shared__ float sm[];
    float* xc_s = sm;
    float* cb_s = sm + 4096;
    float* s_s  = sm + 12544;
    float* x_s  = sm + 16656;
    __shared__ float rinv[16], rmax[16], rsum[16];

    int b = blockIdx.y, n0 = blockIdx.x * 16;
    int t = threadIdx.x, wid = t >> 5, lane = t & 31;

#pragma unroll
    for (int i = 0; i < 16; i++)
        x_s[i * 256 + t] = input[(size_t)(n0 + i) * INFEAT + b * 256 + t];
    __syncthreads();

    for (int i = wid; i < 16; i += 8) {
        float ss = 0.f;
#pragma unroll
        for (int j = 0; j < 8; j++) { float v = x_s[i * 256 + lane + 32 * j]; ss += v * v; }
#pragma unroll
        for (int o = 16; o > 0; o >>= 1) ss += __shfl_xor_sync(0xffffffffu, ss, o);
        if (!lane) rinv[i] = 1.0f / fmaxf(sqrtf(ss), 1e-12f);
    }
    __syncthreads();
#pragma unroll
    for (int i = 0; i < 16; i++) {
        float v = x_s[i * 256 + t] * rinv[i];
        __nv_bfloat16 h, l; split_bf16(v, h, l);
        size_t idx = (size_t)((b << 10) + (n0 + i)) * 256 + t;
        g_xh[idx] = h; g_xl[idx] = l;
    }

    float acc[16];
#pragma unroll
    for (int i = 0; i < 16; i++) acc[i] = 0.f;
    const float* mp = mlp + b * 65536 + t;
#pragma unroll 2
    for (int d = 0; d < 256; d += 4) {
        float m0 = __ldg(mp + (d + 0) * 256);
        float m1 = __ldg(mp + (d + 1) * 256);
        float m2 = __ldg(mp + (d + 2) * 256);
        float m3 = __ldg(mp + (d + 3) * 256);
#pragma unroll
        for (int i = 0; i < 16; i++) {
            float4 xv = *(const float4*)(x_s + i * 256 + d);
            acc[i] += xv.x * m0 + xv.y * m1 + xv.z * m2 + xv.w * m3;
        }
    }
    __syncthreads();
#pragma unroll
    for (int i = 0; i < 16; i++) xc_s[i * 256 + t] = acc[i];
    __syncthreads();

    for (int i = wid; i < 16; i += 8) {
        float m = -3.4e38f;
#pragma unroll
        for (int j = 0; j < 8; j++) m = fmaxf(m, xc_s[i * 256 + lane + 32 * j]);
#pragma unroll
        for (int o = 16; o > 0; o >>= 1) m = fmaxf(m, __shfl_xor_sync(0xffffffffu, m, o));
        float se = 0.f;
#pragma unroll
        for (int j = 0; j < 8; j++) se += expf(xc_s[i * 256 + lane + 32 * j] - m);
#pragma unroll
        for (int o = 16; o > 0; o >>= 1) se += __shfl_xor_sync(0xffffffffu, se, o);
        if (!lane) { rmax[i] = m; rsum[i] = 1.0f / se; }
    }
    __syncthreads();
#pragma unroll
    for (int i = 0; i < 16; i++) {
        float v = expf(acc[i] - rmax[i]) * rsum[i];
        xc_s[i * 256 + t] = v;
        out_xc[(size_t)(n0 + i) * (BOOKS * WORDS) + b * 256 + t] = v;
    }

    int i0 = t >> 5, dl = t & 31;
    const float* cbb = cb + b * 65536;
    for (int c = 0; c < 8; c++) {
        __syncthreads();
#pragma unroll
        for (int d2 = 0; d2 < 32; d2++)
            cb_s[t * 33 + d2] = cbb[(c * 32 + d2) * 256 + t];
        __syncthreads();
        float s0 = 0.f, s1 = 0.f;
#pragma unroll 2
        for (int w = 0; w < 256; w += 4) {
            float c0 = cb_s[(w + 0) * 33 + dl];
            float c1 = cb_s[(w + 1) * 33 + dl];
            float c2 = cb_s[(w + 2) * 33 + dl];
            float c3 = cb_s[(w + 3) * 33 + dl];
            float4 a = *(const float4*)(xc_s + i0 * 256 + w);
            float4 d = *(const float4*)(xc_s + (i0 + 8) * 256 + w);
            s0 += a.x * c0 + a.y * c1 + a.z * c2 + a.w * c3;
            s1 += d.x * c0 + d.y * c1 + d.z * c2 + d.w * c3;
        }
        s_s[i0 * 257 + c * 32 + dl]       = s0;
        s_s[(i0 + 8) * 257 + c * 32 + dl] = s1;
    }
    __syncthreads();

    for (int i = wid; i < 16; i += 8) {
        float ss = 0.f;
#pragma unroll
        for (int j = 0; j < 8; j++) { float v = s_s[i * 257 + lane + 32 * j]; ss += v * v; }
#pragma unroll
        for (int o = 16; o > 0; o >>= 1) ss += __shfl_xor_sync(0xffffffffu, ss, o);
        if (!lane) rinv[i] = 1.0f / fmaxf(sqrtf(ss), 1e-12f);
    }
    __syncthreads();
#pragma unroll
    for (int i = 0; i < 16; i++) {
        float v = s_s[i * 257 + t] * rinv[i];
        __nv_bfloat16 h, l; split_bf16(v, h, l);
        size_t idx = (size_t)((b << 10) + (n0 + i)) * 256 + t;
        g_sh[idx] = h; g_sl[idx] = l;
    }
}

// ---------------------------------------------------------------------------
// Dual GEMM via mma.sync bf16 split-2, warp-specialized by output.
// 512 threads / 16 warps. Block 128(n) x 128(o), BK=32 fp32-k.
// 3-stage circular cp.async pipeline, ONE __syncthreads per stage,
// loads issued before compute so they overlap the MMA burst.
// Warps 0-7: out1 = xn@w.  Warps 8-15: out2 = sn@w.  Warp tile 64x32.
// Stage layout (bf16 rows padded to 40 elems = 80B):
//   xh xl sh sl wh wl  each [128][40] = 10240 B -> stage 61440 B, x3 = 184320 B
// ---------------------------------------------------------------------------
#define TILE_B 10240
#define STAGE_B 61440

__global__ void __launch_bounds__(512, 1)
gemm_mma(const int* __restrict__ label,
         float* __restrict__ out1,
         float* __restrict__ out2) {
    extern __shared__ char smc[];
    __shared__ float winv_s[128];
    uint32_t sb = smem_u32(smc);
    int t = threadIdx.x, wid = t >> 5, lane = t & 31;
    int b = blockIdx.z, n0 = blockIdx.y * 128, o0 = blockIdx.x * 128;

    if (t < 128) winv_s[t] = g_winv[b * OUTF + o0 + t];

    const __nv_bfloat16* pxh = g_xh + (size_t)((b << 10) + n0) * 256;
    const __nv_bfloat16* pxl = g_xl + (size_t)((b << 10) + n0) * 256;
    const __nv_bfloat16* psh = g_sh + (size_t)((b << 10) + n0) * 256;
    const __nv_bfloat16* psl = g_sl + (size_t)((b << 10) + n0) * 256;
    const __nv_bfloat16* pwh = g_wh + ((size_t)b * OUTF + o0) * 256;
    const __nv_bfloat16* pwl = g_wl + ((size_t)b * OUTF + o0) * 256;

    int lrow = t >> 2, lseg = t & 3;          // 512 threads cover 128 rows x 4 segs
    uint32_t cpo = (uint32_t)(lrow * 80 + lseg * 16);
    int ge = lrow * 256 + lseg * 8;

#define LOAD_STAGE(chunk, buf)                                              \
    {                                                                       \
        uint32_t base_ = sb + (uint32_t)(buf) * STAGE_B;                    \
        int g_ = ge + (chunk) * 32;                                         \
        cp16(base_ + cpo,              pxh + g_);                           \
        cp16(base_ + TILE_B + cpo,     pxl + g_);                           \
        cp16(base_ + 2 * TILE_B + cpo, psh + g_);                           \
        cp16(base_ + 3 * TILE_B + cpo, psl + g_);                           \
        cp16(base_ + 4 * TILE_B + cpo, pwh + g_);                           \
        cp16(base_ + 5 * TILE_B + cpo, pwl + g_);                           \
        cp_commit();                                                        \
    }

    int wg  = wid >> 3;            // 0: x->out1, 1: s->out2
    int wl8 = wid & 7;
    int wm = wl8 & 1, wo = wl8 >> 1;
    int m0 = wm * 64, ow0 = wo * 32;
    uint32_t aoff_h = (uint32_t)(wg * 2) * TILE_B;       // xh or sh plane
    uint32_t aoff_l = aoff_h + TILE_B;                   // xl or sl plane

    float acc[4][4][4];
#pragma unroll
    for (int mt = 0; mt < 4; mt++)
#pragma unroll
        for (int ot = 0; ot < 4; ot++)
#pragma unroll
            for (int q = 0; q < 4; q++) acc[mt][ot][q] = 0.f;

    uint32_t a_row = (uint32_t)(m0 + (lane & 7) + ((lane >> 3) & 1) * 8);
    uint32_t b_row = (uint32_t)(ow0 + (lane & 7) + ((lane >> 4) & 1) * 8);

    LOAD_STAGE(0, 0)
    LOAD_STAGE(1, 1)

    int buf = 0;
    for (int i = 0; i < 8; i++) {
        if (i < 7) cp_wait1(); else cp_wait0();
        __syncthreads();
        // issue next-next stage loads BEFORE compute: overlap with MMA burst
        if (i + 2 < 8) {
            int nb = buf + 2; if (nb >= 3) nb -= 3;
            LOAD_STAGE(i + 2, nb)
        }
        uint32_t base = sb + (uint32_t)buf * STAGE_B;

#pragma unroll
        for (int kk = 0; kk < 32; kk += 16) {
            uint32_t a_addr = base + a_row * 80 + (uint32_t)((kk + ((lane >> 4) & 1) * 8) * 2);
            uint32_t b_addr = base + b_row * 80 + (uint32_t)((kk + ((lane >> 3) & 1) * 8) * 2);

            uint32_t fwh[2][4], fwl[2][4];   // pair p covers ot=2p, 2p+1
#pragma unroll
            for (int p = 0; p < 2; p++) {
                uint32_t bo = b_addr + (uint32_t)(p * 16 * 80);
                ldm4(fwh[p], bo + 4 * TILE_B);
                ldm4(fwl[p], bo + 5 * TILE_B);
            }
#pragma unroll
            for (int mt = 0; mt < 4; mt++) {
                uint32_t ao = a_addr + (uint32_t)(mt * 16 * 80);
                uint32_t fah[4], fal[4];
                ldm4(fah, ao + aoff_h);
                ldm4(fal, ao + aoff_l);
                // term-major: RAW distance 4 on each accumulator
#pragma unroll
                for (int ot = 0; ot < 4; ot++)
                    mma16816(acc[mt][ot], fah, &fwh[ot >> 1][(ot & 1) * 2]);
#pragma unroll
                for (int ot = 0; ot < 4; ot++)
                    mma16816(acc[mt][ot], fah, &fwl[ot >> 1][(ot & 1) * 2]);
#pragma unroll
                for (int ot = 0; ot < 4; ot++)
                    mma16816(acc[mt][ot], fal, &fwh[ot >> 1][(ot & 1) * 2]);
            }
        }
        buf++; if (buf >= 3) buf = 0;
    }

    // ---- epilogue: each warp group writes its own output
    float* op = wg ? out2 : out1;
#pragma unroll
    for (int mt = 0; mt < 4; mt++) {
        int r  = n0 + m0 + mt * 16 + (lane >> 2);
        int la = label[r], lb = label[r + 8];
        size_t ro  = (size_t)r * (BOOKS * OUTF) + (size_t)b * OUTF;
        size_t ro8 = ro + (size_t)8 * (BOOKS * OUTF);
#pragma unroll
        for (int ot = 0; ot < 4; ot++) {
            int oc = ow0 + ot * 8 + 2 * (lane & 3);
            int o  = o0 + oc;
            float wi0 = winv_s[oc], wi1 = winv_s[oc + 1];
            float* A = acc[mt][ot];
            float v;
            float2 u;
            v = fminf(fmaxf(A[0] * wi0, -1.f), 1.f); if (la == o)     v -= .5f; u.x = 30.f * v;
            v = fminf(fmaxf(A[1] * wi1, -1.f), 1.f); if (la == o + 1) v -= .5f; u.y = 30.f * v;
            *(float2*)(op + ro + o) = u;
            v = fminf(fmaxf(A[2] * wi0, -1.f), 1.f); if (lb == o)     v -= .5f; u.x = 30.f * v;
            v = fminf(fmaxf(A[3] * wi1, -1.f), 1.f); if (lb == o + 1) v -= .5f; u.y = 30.f * v;
            *(float2*)(op + ro8 + o) = u;
        }
    }
}

// ---------------------------------------------------------------------------
extern "C" void kernel_launch(void* const* d_in, const int* in_sizes, int n_in,
                              void* d_out, int out_size) {
    const float* input  = (const float*)d_in[0];
    const int*   label  = (const int*)d_in[1];     // int32 (JAX default x64 off)
    const float* weight = (const float*)d_in[2];
    const float* mlp    = (const float*)d_in[3];
    const float* cb     = (const float*)d_in[4];

    float* out  = (float*)d_out;
    float* out1 = out;                                    // [1024][8][4096]
    float* out2 = out + (size_t)NROWS * BOOKS * OUTF;     // [1024][8][4096]
    float* out3 = out + (size_t)2 * NROWS * BOOKS * OUTF; // [1024][8][256]

    cudaFuncSetAttribute(bookA_kernel, cudaFuncAttributeMaxDynamicSharedMemorySize, 83008);
    cudaFuncSetAttribute(gemm_mma, cudaFuncAttributeMaxDynamicSharedMemorySize, 3 * STAGE_B);

    wprep_kernel<<<(BOOKS * OUTF) / 8, 256>>>(weight);
    bookA_kernel<<<dim3(NROWS / 16, BOOKS), 256, 83008>>>(input, mlp, cb, out3);
    gemm_mma<<<dim3(OUTF / 128, NROWS / 128, BOOKS), 512, 3 * STAGE_B>>>(label, out1, out2);
}

// round 10
// speedup vs baseline: 1.8064x; 1.1712x over previous
#include <cuda_runtime.h>
#include <cuda_fp16.h>
#include <cstdint>

#define BOOKS 8
#define NROWS 1024
#define INFEAT 2048
#define OUTF 4096
#define LW 256
#define WORDS 256

// Scratch (device globals; no runtime allocation allowed)
__device__ __half g_xh[BOOKS * NROWS * LW];
__device__ __half g_xl[BOOKS * NROWS * LW];
__device__ __half g_sh[BOOKS * NROWS * LW];
__device__ __half g_sl[BOOKS * NROWS * LW];
__device__ __half g_w [BOOKS * OUTF * LW];
__device__ float g_winv[BOOKS * OUTF];

// ===========================================================================
// helpers
// ===========================================================================
__device__ __forceinline__ uint32_t smem_u32(const void* p) {
    uint32_t a;
    asm("{ .reg .u64 t; cvta.to.shared.u64 t, %1; cvt.u32.u64 %0, t; }" : "=r"(a) : "l"(p));
    return a;
}
__device__ __forceinline__ void cp16(uint32_t dst, const void* src) {
    asm volatile("cp.async.cg.shared.global [%0], [%1], 16;" :: "r"(dst), "l"(src));
}
__device__ __forceinline__ void cp_commit() { asm volatile("cp.async.commit_group;"); }
__device__ __forceinline__ void cp_wait1()  { asm volatile("cp.async.wait_group 1;"); }
__device__ __forceinline__ void cp_wait0()  { asm volatile("cp.async.wait_group 0;"); }

__device__ __forceinline__ void ldm4(uint32_t* r, uint32_t addr) {
    asm volatile("ldmatrix.sync.aligned.m8n8.x4.shared.b16 {%0,%1,%2,%3}, [%4];"
                 : "=r"(r[0]), "=r"(r[1]), "=r"(r[2]), "=r"(r[3]) : "r"(addr));
}
__device__ __forceinline__ void mma16816f(float* d, const uint32_t* a, const uint32_t* b) {
    asm volatile(
        "mma.sync.aligned.m16n8k16.row.col.f32.f16.f16.f32 "
        "{%0,%1,%2,%3}, {%4,%5,%6,%7}, {%8,%9}, {%0,%1,%2,%3};"
        : "+f"(d[0]), "+f"(d[1]), "+f"(d[2]), "+f"(d[3])
        : "r"(a[0]), "r"(a[1]), "r"(a[2]), "r"(a[3]), "r"(b[0]), "r"(b[1]));
}
__device__ __forceinline__ void split_f16(float v, __half& h, __half& l) {
    h = __float2half(v);
    l = __float2half(v - __half2float(h));
}

// ---------------------------------------------------------------------------
// wprep: winv + fp16 weight plane, single pass. 1 warp per row.
// ---------------------------------------------------------------------------
__global__ void wprep_kernel(const float* __restrict__ weight) {
    int row  = blockIdx.x * 8 + (threadIdx.x >> 5);
    int lane = threadIdx.x & 31;
    const float4* w4 = (const float4*)(weight + (size_t)row * LW);
    float ss = 0.f;
    float4 v[2];
#pragma unroll
    for (int j = 0; j < 2; j++) {
        v[j] = w4[lane + 32 * j];
        ss += v[j].x * v[j].x + v[j].y * v[j].y + v[j].z * v[j].z + v[j].w * v[j].w;
    }
#pragma unroll
    for (int o = 16; o > 0; o >>= 1) ss += __shfl_xor_sync(0xffffffffu, ss, o);
    if (lane == 0) g_winv[row] = 1.0f / fmaxf(sqrtf(ss), 1e-12f);
#pragma unroll
    for (int j = 0; j < 2; j++) {
        size_t i2 = (size_t)row * (LW / 2) + (lane + 32 * j) * 2;
        ((__half2*)g_w)[i2]     = __half2(__float2half(v[j].x), __float2half(v[j].y));
        ((__half2*)g_w)[i2 + 1] = __half2(__float2half(v[j].z), __float2half(v[j].w));
    }
}

// ---------------------------------------------------------------------------
// bookA: xn, softmax(x@mlp)->xc, s=cb@xc, sn; writes fp16 hi/lo planes.
// ---------------------------------------------------------------------------
__global__ void bookA_kernel(const float* __restrict__ input,
                             const float* __restrict__ mlp,
                             const float* __restrict__ cb,
                             float* __restrict__ out_xc) {
    extern __shared__ float sm[];
    float* xc_s = sm;
    float* cb_s = sm + 4096;
    float* s_s  = sm + 12544;
    float* x_s  = sm + 16656;
    __shared__ float rinv[16], rmax[16], rsum[16];

    int b = blockIdx.y, n0 = blockIdx.x * 16;
    int t = threadIdx.x, wid = t >> 5, lane = t & 31;

#pragma unroll
    for (int i = 0; i < 16; i++)
        x_s[i * 256 + t] = input[(size_t)(n0 + i) * INFEAT + b * 256 + t];
    __syncthreads();

    for (int i = wid; i < 16; i += 8) {
        float ss = 0.f;
#pragma unroll
        for (int j = 0; j < 8; j++) { float v = x_s[i * 256 + lane + 32 * j]; ss += v * v; }
#pragma unroll
        for (int o = 16; o > 0; o >>= 1) ss += __shfl_xor_sync(0xffffffffu, ss, o);
        if (!lane) rinv[i] = 1.0f / fmaxf(sqrtf(ss), 1e-12f);
    }
    __syncthreads();
#pragma unroll
    for (int i = 0; i < 16; i++) {
        float v = x_s[i * 256 + t] * rinv[i];
        __half h, l; split_f16(v, h, l);
        size_t idx = (size_t)((b << 10) + (n0 + i)) * 256 + t;
        g_xh[idx] = h; g_xl[idx] = l;
    }

    float acc[16];
#pragma unroll
    for (int i = 0; i < 16; i++) acc[i] = 0.f;
    const float* mp = mlp + b * 65536 + t;
#pragma unroll 2
    for (int d = 0; d < 256; d += 4) {
        float m0 = __ldg(mp + (d + 0) * 256);
        float m1 = __ldg(mp + (d + 1) * 256);
        float m2 = __ldg(mp + (d + 2) * 256);
        float m3 = __ldg(mp + (d + 3) * 256);
#pragma unroll
        for (int i = 0; i < 16; i++) {
            float4 xv = *(const float4*)(x_s + i * 256 + d);
            acc[i] += xv.x * m0 + xv.y * m1 + xv.z * m2 + xv.w * m3;
        }
    }
    __syncthreads();
#pragma unroll
    for (int i = 0; i < 16; i++) xc_s[i * 256 + t] = acc[i];
    __syncthreads();

    for (int i = wid; i < 16; i += 8) {
        float m = -3.4e38f;
#pragma unroll
        for (int j = 0; j < 8; j++) m = fmaxf(m, xc_s[i * 256 + lane + 32 * j]);
#pragma unroll
        for (int o = 16; o > 0; o >>= 1) m = fmaxf(m, __shfl_xor_sync(0xffffffffu, m, o));
        float se = 0.f;
#pragma unroll
        for (int j = 0; j < 8; j++) se += expf(xc_s[i * 256 + lane + 32 * j] - m);
#pragma unroll
        for (int o = 16; o > 0; o >>= 1) se += __shfl_xor_sync(0xffffffffu, se, o);
        if (!lane) { rmax[i] = m; rsum[i] = 1.0f / se; }
    }
    __syncthreads();
#pragma unroll
    for (int i = 0; i < 16; i++) {
        float v = expf(acc[i] - rmax[i]) * rsum[i];
        xc_s[i * 256 + t] = v;
        out_xc[(size_t)(n0 + i) * (BOOKS * WORDS) + b * 256 + t] = v;
    }

    int i0 = t >> 5, dl = t & 31;
    const float* cbb = cb + b * 65536;
    for (int c = 0; c < 8; c++) {
        __syncthreads();
#pragma unroll
        for (int d2 = 0; d2 < 32; d2++)
            cb_s[t * 33 + d2] = cbb[(c * 32 + d2) * 256 + t];
        __syncthreads();
        float s0 = 0.f, s1 = 0.f;
#pragma unroll 2
        for (int w = 0; w < 256; w += 4) {
            float c0 = cb_s[(w + 0) * 33 + dl];
            float c1 = cb_s[(w + 1) * 33 + dl];
            float c2 = cb_s[(w + 2) * 33 + dl];
            float c3 = cb_s[(w + 3) * 33 + dl];
            float4 a = *(const float4*)(xc_s + i0 * 256 + w);
            float4 d = *(const float4*)(xc_s + (i0 + 8) * 256 + w);
            s0 += a.x * c0 + a.y * c1 + a.z * c2 + a.w * c3;
            s1 += d.x * c0 + d.y * c1 + d.z * c2 + d.w * c3;
        }
        s_s[i0 * 257 + c * 32 + dl]       = s0;
        s_s[(i0 + 8) * 257 + c * 32 + dl] = s1;
    }
    __syncthreads();

    for (int i = wid; i < 16; i += 8) {
        float ss = 0.f;
#pragma unroll
        for (int j = 0; j < 8; j++) { float v = s_s[i * 257 + lane + 32 * j]; ss += v * v; }
#pragma unroll
        for (int o = 16; o > 0; o >>= 1) ss += __shfl_xor_sync(0xffffffffu, ss, o);
        if (!lane) rinv[i] = 1.0f / fmaxf(sqrtf(ss), 1e-12f);
    }
    __syncthreads();
#pragma unroll
    for (int i = 0; i < 16; i++) {
        float v = s_s[i * 257 + t] * rinv[i];
        __half h, l; split_f16(v, h, l);
        size_t idx = (size_t)((b << 10) + (n0 + i)) * 256 + t;
        g_sh[idx] = h; g_sl[idx] = l;
    }
}

// ---------------------------------------------------------------------------
// Dual GEMM via mma.sync fp16 split-2 (x split, w single plane).
// 512 threads / 16 warps, warp-specialized: warps 0-7 out1(x), 8-15 out2(s).
// Block 128(n) x 128(o), BK=32, 3-stage circular cp.async pipeline,
// one __syncthreads per stage, loads issued before compute.
// Stage layout (fp16, rows padded to 40 elems = 80B):
//   xh xl sh sl w   each [128][40] = 10240 B -> stage 51200 B, x3 = 153600 B
// ---------------------------------------------------------------------------
#define TILE_B 10240
#define STAGE_B 51200

__global__ void __launch_bounds__(512, 1)
gemm_mma(const int* __restrict__ label,
         float* __restrict__ out1,
         float* __restrict__ out2) {
    extern __shared__ char smc[];
    __shared__ float winv_s[128];
    uint32_t sb = smem_u32(smc);
    int t = threadIdx.x, wid = t >> 5, lane = t & 31;
    int b = blockIdx.z, n0 = blockIdx.y * 128, o0 = blockIdx.x * 128;

    if (t < 128) winv_s[t] = g_winv[b * OUTF + o0 + t];

    const __half* pxh = g_xh + (size_t)((b << 10) + n0) * 256;
    const __half* pxl = g_xl + (size_t)((b << 10) + n0) * 256;
    const __half* psh = g_sh + (size_t)((b << 10) + n0) * 256;
    const __half* psl = g_sl + (size_t)((b << 10) + n0) * 256;
    const __half* pw  = g_w  + ((size_t)b * OUTF + o0) * 256;

    int lrow = t >> 2, lseg = t & 3;          // 512 threads cover 128 rows x 4 segs
    uint32_t cpo = (uint32_t)(lrow * 80 + lseg * 16);
    int ge = lrow * 256 + lseg * 8;

#define LOAD_STAGE(chunk, buf)                                              \
    {                                                                       \
        uint32_t base_ = sb + (uint32_t)(buf) * STAGE_B;                    \
        int g_ = ge + (chunk) * 32;                                         \
        cp16(base_ + cpo,              pxh + g_);                           \
        cp16(base_ + TILE_B + cpo,     pxl + g_);                           \
        cp16(base_ + 2 * TILE_B + cpo, psh + g_);                           \
        cp16(base_ + 3 * TILE_B + cpo, psl + g_);                           \
        cp16(base_ + 4 * TILE_B + cpo, pw  + g_);                           \
        cp_commit();                                                        \
    }

    int wg  = wid >> 3;            // 0: x->out1, 1: s->out2
    int wl8 = wid & 7;
    int wm = wl8 & 1, wo = wl8 >> 1;
    int m0 = wm * 64, ow0 = wo * 32;
    uint32_t aoff_h = (uint32_t)(wg * 2) * TILE_B;       // xh or sh plane
    uint32_t aoff_l = aoff_h + TILE_B;                   // xl or sl plane

    float acc[4][4][4];
#pragma unroll
    for (int mt = 0; mt < 4; mt++)
#pragma unroll
        for (int ot = 0; ot < 4; ot++)
#pragma unroll
            for (int q = 0; q < 4; q++) acc[mt][ot][q] = 0.f;

    uint32_t a_row = (uint32_t)(m0 + (lane & 7) + ((lane >> 3) & 1) * 8);
    uint32_t b_row = (uint32_t)(ow0 + (lane & 7) + ((lane >> 4) & 1) * 8);

    LOAD_STAGE(0, 0)
    LOAD_STAGE(1, 1)

    int buf = 0;
    for (int i = 0; i < 8; i++) {
        if (i < 7) cp_wait1(); else cp_wait0();
        __syncthreads();
        // issue next-next stage loads BEFORE compute: overlap with MMA burst
        if (i + 2 < 8) {
            int nb = buf + 2; if (nb >= 3) nb -= 3;
            LOAD_STAGE(i + 2, nb)
        }
        uint32_t base = sb + (uint32_t)buf * STAGE_B;

#pragma unroll
        for (int kk = 0; kk < 32; kk += 16) {
            uint32_t a_addr = base + a_row * 80 + (uint32_t)((kk + ((lane >> 4) & 1) * 8) * 2);
            uint32_t b_addr = base + b_row * 80 + (uint32_t)((kk + ((lane >> 3) & 1) * 8) * 2);

            uint32_t fw[2][4];               // pair p covers ot=2p, 2p+1
#pragma unroll
            for (int p = 0; p < 2; p++)
                ldm4(fw[p], b_addr + (uint32_t)(p * 16 * 80) + 4 * TILE_B);

#pragma unroll
            for (int mt = 0; mt < 4; mt++) {
                uint32_t ao = a_addr + (uint32_t)(mt * 16 * 80);
                uint32_t fah[4], fal[4];
                ldm4(fah, ao + aoff_h);
                ldm4(fal, ao + aoff_l);
                // term-major: RAW distance 4 on each accumulator
#pragma unroll
                for (int ot = 0; ot < 4; ot++)
                    mma16816f(acc[mt][ot], fah, &fw[ot >> 1][(ot & 1) * 2]);
#pragma unroll
                for (int ot = 0; ot < 4; ot++)
                    mma16816f(acc[mt][ot], fal, &fw[ot >> 1][(ot & 1) * 2]);
            }
        }
        buf++; if (buf >= 3) buf = 0;
    }

    // ---- epilogue: each warp group writes its own output
    float* op = wg ? out2 : out1;
#pragma unroll
    for (int mt = 0; mt < 4; mt++) {
        int r  = n0 + m0 + mt * 16 + (lane >> 2);
        int la = label[r], lb = label[r + 8];
        size_t ro  = (size_t)r * (BOOKS * OUTF) + (size_t)b * OUTF;
        size_t ro8 = ro + (size_t)8 * (BOOKS * OUTF);
#pragma unroll
        for (int ot = 0; ot < 4; ot++) {
            int oc = ow0 + ot * 8 + 2 * (lane & 3);
            int o  = o0 + oc;
            float wi0 = winv_s[oc], wi1 = winv_s[oc + 1];
            float* A = acc[mt][ot];
            float v;
            float2 u;
            v = fminf(fmaxf(A[0] * wi0, -1.f), 1.f); if (la == o)     v -= .5f; u.x = 30.f * v;
            v = fminf(fmaxf(A[1] * wi1, -1.f), 1.f); if (la == o + 1) v -= .5f; u.y = 30.f * v;
            *(float2*)(op + ro + o) = u;
            v = fminf(fmaxf(A[2] * wi0, -1.f), 1.f); if (lb == o)     v -= .5f; u.x = 30.f * v;
            v = fminf(fmaxf(A[3] * wi1, -1.f), 1.f); if (lb == o + 1) v -= .5f; u.y = 30.f * v;
            *(float2*)(op + ro8 + o) = u;
        }
    }
}

// ---------------------------------------------------------------------------
extern "C" void kernel_launch(void* const* d_in, const int* in_sizes, int n_in,
                              void* d_out, int out_size) {
    const float* input  = (const float*)d_in[0];
    const int*   label  = (const int*)d_in[1];     // int32 (JAX default x64 off)
    const float* weight = (const float*)d_in[2];
    const float* mlp    = (const float*)d_in[3];
    const float* cb     = (const float*)d_in[4];

    float* out  = (float*)d_out;
    float* out1 = out;                                    // [1024][8][4096]
    float* out2 = out + (size_t)NROWS * BOOKS * OUTF;     // [1024][8][4096]
    float* out3 = out + (size_t)2 * NROWS * BOOKS * OUTF; // [1024][8][256]

    cudaFuncSetAttribute(bookA_kernel, cudaFuncAttributeMaxDynamicSharedMemorySize, 83008);
    cudaFuncSetAttribute(gemm_mma, cudaFuncAttributeMaxDynamicSharedMemorySize, 3 * STAGE_B);

    wprep_kernel<<<(BOOKS * OUTF) / 8, 256>>>(weight);
    bookA_kernel<<<dim3(NROWS / 16, BOOKS), 256, 83008>>>(input, mlp, cb, out3);
    gemm_mma<<<dim3(OUTF / 128, NROWS / 128, BOOKS), 512, 3 * STAGE_B>>>(label, out1, out2);
}

// round 14
// speedup vs baseline: 2.0564x; 1.1384x over previous
#include <cuda_runtime.h>
#include <cuda_fp16.h>
#include <cstdint>

#define BOOKS 8
#define NROWS 1024
#define INFEAT 2048
#define OUTF 4096
#define LW 256
#define WORDS 256

// Scratch (device globals; no runtime allocation allowed)
__device__ __half g_xh[BOOKS * NROWS * LW];
__device__ __half g_xl[BOOKS * NROWS * LW];    // scaled by 2048
__device__ __half g_sh[BOOKS * NROWS * LW];
__device__ __half g_sl[BOOKS * NROWS * LW];    // scaled by 2048
__device__ __half g_w [BOOKS * OUTF * LW];
__device__ float g_winv[BOOKS * OUTF];
__device__ float g_cbT[BOOKS * WORDS * LW];    // cb transposed: [b][w][d]

#define LO_SCALE 2048.0f
#define LO_INV   4.8828125e-4f

// ===========================================================================
// helpers
// ===========================================================================
__device__ __forceinline__ uint32_t smem_u32(const void* p) {
    uint32_t a;
    asm("{ .reg .u64 t; cvta.to.shared.u64 t, %1; cvt.u32.u64 %0, t; }" : "=r"(a) : "l"(p));
    return a;
}
__device__ __forceinline__ void cp16(uint32_t dst, const void* src) {
    asm volatile("cp.async.cg.shared.global [%0], [%1], 16;" :: "r"(dst), "l"(src));
}
__device__ __forceinline__ void cp_commit() { asm volatile("cp.async.commit_group;"); }
__device__ __forceinline__ void cp_wait1()  { asm volatile("cp.async.wait_group 1;"); }
__device__ __forceinline__ void cp_wait0()  { asm volatile("cp.async.wait_group 0;"); }

__device__ __forceinline__ void ldm4(uint32_t* r, uint32_t addr) {
    asm volatile("ldmatrix.sync.aligned.m8n8.x4.shared.b16 {%0,%1,%2,%3}, [%4];"
                 : "=r"(r[0]), "=r"(r[1]), "=r"(r[2]), "=r"(r[3]) : "r"(addr));
}
__device__ __forceinline__ void mma16816f(float* d, const uint32_t* a, const uint32_t* b) {
    asm volatile(
        "mma.sync.aligned.m16n8k16.row.col.f32.f16.f16.f32 "
        "{%0,%1,%2,%3}, {%4,%5,%6,%7}, {%8,%9}, {%0,%1,%2,%3};"
        : "+f"(d[0]), "+f"(d[1]), "+f"(d[2]), "+f"(d[3])
        : "r"(a[0]), "r"(a[1]), "r"(a[2]), "r"(a[3]), "r"(b[0]), "r"(b[1]));
}
__device__ __forceinline__ void mma16816h(uint32_t* d, const uint32_t* a, const uint32_t* b) {
    asm volatile(
        "mma.sync.aligned.m16n8k16.row.col.f16.f16.f16.f16 "
        "{%0,%1}, {%2,%3,%4,%5}, {%6,%7}, {%0,%1};"
        : "+r"(d[0]), "+r"(d[1])
        : "r"(a[0]), "r"(a[1]), "r"(a[2]), "r"(a[3]), "r"(b[0]), "r"(b[1]));
}
__device__ __forceinline__ void split_f16(float v, __half& h, __half& l) {
    h = __float2half(v);
    l = __float2half((v - __half2float(h)) * LO_SCALE);
}

// ---------------------------------------------------------------------------
// wprep: winv + fp16 weight plane, single pass. 1 warp per row.
// ---------------------------------------------------------------------------
__global__ void wprep_kernel(const float* __restrict__ weight) {
    int row  = blockIdx.x * 8 + (threadIdx.x >> 5);
    int lane = threadIdx.x & 31;
    const float4* w4 = (const float4*)(weight + (size_t)row * LW);
    float ss = 0.f;
    float4 v[2];
#pragma unroll
    for (int j = 0; j < 2; j++) {
        v[j] = w4[lane + 32 * j];
        ss += v[j].x * v[j].x + v[j].y * v[j].y + v[j].z * v[j].z + v[j].w * v[j].w;
    }
#pragma unroll
    for (int o = 16; o > 0; o >>= 1) ss += __shfl_xor_sync(0xffffffffu, ss, o);
    if (lane == 0) g_winv[row] = 1.0f / fmaxf(sqrtf(ss), 1e-12f);
#pragma unroll
    for (int j = 0; j < 2; j++) {
        size_t i2 = (size_t)row * (LW / 2) + (lane + 32 * j) * 2;
        ((__half2*)g_w)[i2]     = __half2(__float2half(v[j].x), __float2half(v[j].y));
        ((__half2*)g_w)[i2 + 1] = __half2(__float2half(v[j].z), __float2half(v[j].w));
    }
}

// ---------------------------------------------------------------------------
// cbT: transpose codebooks [b][d][w] -> [b][w][d]. Tiled 32x32.
// ---------------------------------------------------------------------------
__global__ void cbT_kernel(const float* __restrict__ cb) {
    __shared__ float tile[32][33];
    int b = blockIdx.z;
    int d0 = blockIdx.x * 32, w0 = blockIdx.y * 32;
    int tx = threadIdx.x, ty = threadIdx.y;   // (32, 8)
    const float* src = cb + b * 65536;
    float* dst = g_cbT + b * 65536;
#pragma unroll
    for (int j = ty; j < 32; j += 8)
        tile[j][tx] = src[(d0 + j) * 256 + w0 + tx];
    __syncthreads();
#pragma unroll
    for (int j = ty; j < 32; j += 8)
        dst[(w0 + j) * 256 + d0 + tx] = tile[tx][j];
}

// ---------------------------------------------------------------------------
// bookA: xn, softmax(x@mlp)->xc, s=cbT@xc, sn; writes fp16 hi/lo planes.
// smem: xc_s[16][256] @0, s_s[16][257] @4096, x_s[16][256] @8208
// total 12304 floats = 49216 B -> higher occupancy.
// ---------------------------------------------------------------------------
__global__ void bookA_kernel(const float* __restrict__ input,
                             const float* __restrict__ mlp,
                             float* __restrict__ out_xc) {
    extern __shared__ float sm[];
    float* xc_s = sm;
    float* s_s  = sm + 4096;
    float* x_s  = sm + 8208;
    __shared__ float rinv[16], rmax[16], rsum[16];

    int b = blockIdx.y, n0 = blockIdx.x * 16;
    int t = threadIdx.x, wid = t >> 5, lane = t & 31;

#pragma unroll
    for (int i = 0; i < 16; i++)
        x_s[i * 256 + t] = input[(size_t)(n0 + i) * INFEAT + b * 256 + t];
    __syncthreads();

    for (int i = wid; i < 16; i += 8) {
        float ss = 0.f;
#pragma unroll
        for (int j = 0; j < 8; j++) { float v = x_s[i * 256 + lane + 32 * j]; ss += v * v; }
#pragma unroll
        for (int o = 16; o > 0; o >>= 1) ss += __shfl_xor_sync(0xffffffffu, ss, o);
        if (!lane) rinv[i] = 1.0f / fmaxf(sqrtf(ss), 1e-12f);
    }
    __syncthreads();
#pragma unroll
    for (int i = 0; i < 16; i++) {
        float v = x_s[i * 256 + t] * rinv[i];
        __half h, l; split_f16(v, h, l);
        size_t idx = (size_t)((b << 10) + (n0 + i)) * 256 + t;
        g_xh[idx] = h; g_xl[idx] = l;
    }

    float acc[16];
#pragma unroll
    for (int i = 0; i < 16; i++) acc[i] = 0.f;
    const float* mp = mlp + b * 65536 + t;
#pragma unroll 2
    for (int d = 0; d < 256; d += 4) {
        float m0 = __ldg(mp + (d + 0) * 256);
        float m1 = __ldg(mp + (d + 1) * 256);
        float m2 = __ldg(mp + (d + 2) * 256);
        float m3 = __ldg(mp + (d + 3) * 256);
#pragma unroll
        for (int i = 0; i < 16; i++) {
            float4 xv = *(const float4*)(x_s + i * 256 + d);
            acc[i] += xv.x * m0 + xv.y * m1 + xv.z * m2 + xv.w * m3;
        }
    }
    __syncthreads();
#pragma unroll
    for (int i = 0; i < 16; i++) xc_s[i * 256 + t] = acc[i];
    __syncthreads();

    for (int i = wid; i < 16; i += 8) {
        float m = -3.4e38f;
#pragma unroll
        for (int j = 0; j < 8; j++) m = fmaxf(m, xc_s[i * 256 + lane + 32 * j]);
#pragma unroll
        for (int o = 16; o > 0; o >>= 1) m = fmaxf(m, __shfl_xor_sync(0xffffffffu, m, o));
        float se = 0.f;
#pragma unroll
        for (int j = 0; j < 8; j++) se += expf(xc_s[i * 256 + lane + 32 * j] - m);
#pragma unroll
        for (int o = 16; o > 0; o >>= 1) se += __shfl_xor_sync(0xffffffffu, se, o);
        if (!lane) { rmax[i] = m; rsum[i] = 1.0f / se; }
    }
    __syncthreads();
#pragma unroll
    for (int i = 0; i < 16; i++) {
        float v = expf(acc[i] - rmax[i]) * rsum[i];
        xc_s[i * 256 + t] = v;
        out_xc[(size_t)(n0 + i) * (BOOKS * WORDS) + b * 256 + t] = v;
    }
    __syncthreads();

    // s[i][d] = sum_w cbT[w][d] * xc[i][w]  — thread t owns d=t, coalesced __ldg
    float sacc[16];
#pragma unroll
    for (int i = 0; i < 16; i++) sacc[i] = 0.f;
    const float* cp = g_cbT + b * 65536 + t;
#pragma unroll 2
    for (int w = 0; w < 256; w += 4) {
        float c0 = __ldg(cp + (w + 0) * 256);
        float c1 = __ldg(cp + (w + 1) * 256);
        float c2 = __ldg(cp + (w + 2) * 256);
        float c3 = __ldg(cp + (w + 3) * 256);
#pragma unroll
        for (int i = 0; i < 16; i++) {
            float4 a = *(const float4*)(xc_s + i * 256 + w);
            sacc[i] += a.x * c0 + a.y * c1 + a.z * c2 + a.w * c3;
        }
    }
#pragma unroll
    for (int i = 0; i < 16; i++) s_s[i * 257 + t] = sacc[i];
    __syncthreads();

    for (int i = wid; i < 16; i += 8) {
        float ss = 0.f;
#pragma unroll
        for (int j = 0; j < 8; j++) { float v = s_s[i * 257 + lane + 32 * j]; ss += v * v; }
#pragma unroll
        for (int o = 16; o > 0; o >>= 1) ss += __shfl_xor_sync(0xffffffffu, ss, o);
        if (!lane) rinv[i] = 1.0f / fmaxf(sqrtf(ss), 1e-12f);
    }
    __syncthreads();
#pragma unroll
    for (int i = 0; i < 16; i++) {
        float v = s_s[i * 257 + t] * rinv[i];
        __half h, l; split_f16(v, h, l);
        size_t idx = (size_t)((b << 10) + (n0 + i)) * 256 + t;
        g_sh[idx] = h; g_sl[idx] = l;
    }
}

// ---------------------------------------------------------------------------
// Dual GEMM: fp16 split-2, hi-term fp32-acc MMA + lo-term fp16-acc MMA.
// 512 threads / 16 warps, warp-specialized: warps 0-7 out1(x), 8-15 out2(s).
// Block 128(n) x 128(o), BK=32, 3-stage circular cp.async pipeline.
// Stage: xh xl sh sl w, each [128][40] fp16 = 10240 B -> 51200 B, x3.
// ---------------------------------------------------------------------------
#define TILE_B 10240
#define STAGE_B 51200

__global__ void __launch_bounds__(512, 1)
gemm_mma(const int* __restrict__ label,
         float* __restrict__ out1,
         float* __restrict__ out2) {
    extern __shared__ char smc[];
    __shared__ float winv_s[128];
    uint32_t sb = smem_u32(smc);
    int t = threadIdx.x, wid = t >> 5, lane = t & 31;
    int b = blockIdx.z, n0 = blockIdx.y * 128, o0 = blockIdx.x * 128;

    if (t < 128) winv_s[t] = g_winv[b * OUTF + o0 + t];

    const __half* pxh = g_xh + (size_t)((b << 10) + n0) * 256;
    const __half* pxl = g_xl + (size_t)((b << 10) + n0) * 256;
    const __half* psh = g_sh + (size_t)((b << 10) + n0) * 256;
    const __half* psl = g_sl + (size_t)((b << 10) + n0) * 256;
    const __half* pw  = g_w  + ((size_t)b * OUTF + o0) * 256;

    int lrow = t >> 2, lseg = t & 3;
    uint32_t cpo = (uint32_t)(lrow * 80 + lseg * 16);
    int ge = lrow * 256 + lseg * 8;

#define LOAD_STAGE(chunk, buf)                                              \
    {                                                                       \
        uint32_t base_ = sb + (uint32_t)(buf) * STAGE_B;                    \
        int g_ = ge + (chunk) * 32;                                         \
        cp16(base_ + cpo,              pxh + g_);                           \
        cp16(base_ + TILE_B + cpo,     pxl + g_);                           \
        cp16(base_ + 2 * TILE_B + cpo, psh + g_);                           \
        cp16(base_ + 3 * TILE_B + cpo, psl + g_);                           \
        cp16(base_ + 4 * TILE_B + cpo, pw  + g_);                           \
        cp_commit();                                                        \
    }

    int wg  = wid >> 3;            // 0: x->out1, 1: s->out2
    int wl8 = wid & 7;
    int wm = wl8 & 1, wo = wl8 >> 1;
    int m0 = wm * 64, ow0 = wo * 32;
    uint32_t aoff_h = (uint32_t)(wg * 2) * TILE_B;
    uint32_t aoff_l = aoff_h + TILE_B;

    float acc[4][4][4];
    uint32_t accl[4][4][2];
#pragma unroll
    for (int mt = 0; mt < 4; mt++)
#pragma unroll
        for (int ot = 0; ot < 4; ot++) {
#pragma unroll
            for (int q = 0; q < 4; q++) acc[mt][ot][q] = 0.f;
            accl[mt][ot][0] = 0u; accl[mt][ot][1] = 0u;
        }

    uint32_t a_row = (uint32_t)(m0 + (lane & 7) + ((lane >> 3) & 1) * 8);
    uint32_t b_row = (uint32_t)(ow0 + (lane & 7) + ((lane >> 4) & 1) * 8);

    LOAD_STAGE(0, 0)
    LOAD_STAGE(1, 1)

    int buf = 0;
    for (int i = 0; i < 8; i++) {
        if (i < 7) cp_wait1(); else cp_wait0();
        __syncthreads();
        if (i + 2 < 8) {
            int nb = buf + 2; if (nb >= 3) nb -= 3;
            LOAD_STAGE(i + 2, nb)
        }
        uint32_t base = sb + (uint32_t)buf * STAGE_B;

#pragma unroll
        for (int kk = 0; kk < 32; kk += 16) {
            uint32_t a_addr = base + a_row * 80 + (uint32_t)((kk + ((lane >> 4) & 1) * 8) * 2);
            uint32_t b_addr = base + b_row * 80 + (uint32_t)((kk + ((lane >> 3) & 1) * 8) * 2);

            uint32_t fw[2][4];
#pragma unroll
            for (int p = 0; p < 2; p++)
                ldm4(fw[p], b_addr + (uint32_t)(p * 16 * 80) + 4 * TILE_B);

#pragma unroll
            for (int mt = 0; mt < 4; mt++) {
                uint32_t ao = a_addr + (uint32_t)(mt * 16 * 80);
                uint32_t fah[4], fal[4];
                ldm4(fah, ao + aoff_h);
                ldm4(fal, ao + aoff_l);
#pragma unroll
                for (int ot = 0; ot < 4; ot++)
                    mma16816f(acc[mt][ot], fah, &fw[ot >> 1][(ot & 1) * 2]);
#pragma unroll
                for (int ot = 0; ot < 4; ot++)
                    mma16816h(accl[mt][ot], fal, &fw[ot >> 1][(ot & 1) * 2]);
            }
        }
        buf++; if (buf >= 3) buf = 0;
    }

    // ---- epilogue: fold scaled fp16 lo accumulator into fp32 hi
    float* op = wg ? out2 : out1;
#pragma unroll
    for (int mt = 0; mt < 4; mt++) {
        int r  = n0 + m0 + mt * 16 + (lane >> 2);
        int la = label[r], lb = label[r + 8];
        size_t ro  = (size_t)r * (BOOKS * OUTF) + (size_t)b * OUTF;
        size_t ro8 = ro + (size_t)8 * (BOOKS * OUTF);
#pragma unroll
        for (int ot = 0; ot < 4; ot++) {
            int oc = ow0 + ot * 8 + 2 * (lane & 3);
            int o  = o0 + oc;
            float wi0 = winv_s[oc], wi1 = winv_s[oc + 1];
            float* A = acc[mt][ot];
            float2 lo01 = __half22float2(*(const __half2*)&accl[mt][ot][0]);
            float2 lo23 = __half22float2(*(const __half2*)&accl[mt][ot][1]);
            float f0 = A[0] + lo01.x * LO_INV;
            float f1 = A[1] + lo01.y * LO_INV;
            float f2 = A[2] + lo23.x * LO_INV;
            float f3 = A[3] + lo23.y * LO_INV;
            float v;
            float2 u;
            v = fminf(fmaxf(f0 * wi0, -1.f), 1.f); if (la == o)     v -= .5f; u.x = 30.f * v;
            v = fminf(fmaxf(f1 * wi1, -1.f), 1.f); if (la == o + 1) v -= .5f; u.y = 30.f * v;
            *(float2*)(op + ro + o) = u;
            v = fminf(fmaxf(f2 * wi0, -1.f), 1.f); if (lb == o)     v -= .5f; u.x = 30.f * v;
            v = fminf(fmaxf(f3 * wi1, -1.f), 1.f); if (lb == o + 1) v -= .5f; u.y = 30.f * v;
            *(float2*)(op + ro8 + o) = u;
        }
    }
}

// ---------------------------------------------------------------------------
extern "C" void kernel_launch(void* const* d_in, const int* in_sizes, int n_in,
                              void* d_out, int out_size) {
    const float* input  = (const float*)d_in[0];
    const int*   label  = (const int*)d_in[1];     // int32 (JAX default x64 off)
    const float* weight = (const float*)d_in[2];
    const float* mlp    = (const float*)d_in[3];
    const float* cb     = (const float*)d_in[4];

    float* out  = (float*)d_out;
    float* out1 = out;                                    // [1024][8][4096]
    float* out2 = out + (size_t)NROWS * BOOKS * OUTF;     // [1024][8][4096]
    float* out3 = out + (size_t)2 * NROWS * BOOKS * OUTF; // [1024][8][256]

    cudaFuncSetAttribute(bookA_kernel, cudaFuncAttributeMaxDynamicSharedMemorySize, 49216);
    cudaFuncSetAttribute(gemm_mma, cudaFuncAttributeMaxDynamicSharedMemorySize, 3 * STAGE_B);

    wprep_kernel<<<(BOOKS * OUTF) / 8, 256>>>(weight);
    cbT_kernel<<<dim3(8, 8, BOOKS), dim3(32, 8)>>>(cb);
    bookA_kernel<<<dim3(NROWS / 16, BOOKS), 256, 49216>>>(input, mlp, out3);
    gemm_mma<<<dim3(OUTF / 128, NROWS / 128, BOOKS), 512, 3 * STAGE_B>>>(label, out1, out2);
}

// round 15
// speedup vs baseline: 3.0221x; 1.4696x over previous
#include <cuda_runtime.h>
#include <cuda_fp16.h>
#include <cstdint>

#define BOOKS 8
#define NROWS 1024
#define INFEAT 2048
#define OUTF 4096
#define LW 256
#define WORDS 256

// Scratch (device globals; no runtime allocation allowed)
__device__ __half g_x[BOOKS * NROWS * LW];     // fp16(xn)
__device__ __half g_s[BOOKS * NROWS * LW];     // fp16(sn)
__device__ __half g_w[BOOKS * OUTF * LW];      // fp16(weight)
__device__ float g_winv[BOOKS * OUTF];
__device__ float g_cbT[BOOKS * WORDS * LW];    // cb transposed: [b][w][d]

// ===========================================================================
// helpers
// ===========================================================================
__device__ __forceinline__ uint32_t smem_u32(const void* p) {
    uint32_t a;
    asm("{ .reg .u64 t; cvta.to.shared.u64 t, %1; cvt.u32.u64 %0, t; }" : "=r"(a) : "l"(p));
    return a;
}
__device__ __forceinline__ void cp16(uint32_t dst, const void* src) {
    asm volatile("cp.async.cg.shared.global [%0], [%1], 16;" :: "r"(dst), "l"(src));
}
__device__ __forceinline__ void cp_commit() { asm volatile("cp.async.commit_group;"); }
__device__ __forceinline__ void cp_wait1()  { asm volatile("cp.async.wait_group 1;"); }
__device__ __forceinline__ void cp_wait0()  { asm volatile("cp.async.wait_group 0;"); }

__device__ __forceinline__ void ldm4(uint32_t* r, uint32_t addr) {
    asm volatile("ldmatrix.sync.aligned.m8n8.x4.shared.b16 {%0,%1,%2,%3}, [%4];"
                 : "=r"(r[0]), "=r"(r[1]), "=r"(r[2]), "=r"(r[3]) : "r"(addr));
}
__device__ __forceinline__ void mma16816f(float* d, const uint32_t* a, const uint32_t* b) {
    asm volatile(
        "mma.sync.aligned.m16n8k16.row.col.f32.f16.f16.f32 "
        "{%0,%1,%2,%3}, {%4,%5,%6,%7}, {%8,%9}, {%0,%1,%2,%3};"
        : "+f"(d[0]), "+f"(d[1]), "+f"(d[2]), "+f"(d[3])
        : "r"(a[0]), "r"(a[1]), "r"(a[2]), "r"(a[3]), "r"(b[0]), "r"(b[1]));
}

// ---------------------------------------------------------------------------
// wprep: winv + fp16 weight plane, single pass. 1 warp per row.
// ---------------------------------------------------------------------------
__global__ void wprep_kernel(const float* __restrict__ weight) {
    int row  = blockIdx.x * 8 + (threadIdx.x >> 5);
    int lane = threadIdx.x & 31;
    const float4* w4 = (const float4*)(weight + (size_t)row * LW);
    float ss = 0.f;
    float4 v[2];
#pragma unroll
    for (int j = 0; j < 2; j++) {
        v[j] = w4[lane + 32 * j];
        ss += v[j].x * v[j].x + v[j].y * v[j].y + v[j].z * v[j].z + v[j].w * v[j].w;
    }
#pragma unroll
    for (int o = 16; o > 0; o >>= 1) ss += __shfl_xor_sync(0xffffffffu, ss, o);
    if (lane == 0) g_winv[row] = 1.0f / fmaxf(sqrtf(ss), 1e-12f);
#pragma unroll
    for (int j = 0; j < 2; j++) {
        size_t i2 = (size_t)row * (LW / 2) + (lane + 32 * j) * 2;
        ((__half2*)g_w)[i2]     = __half2(__float2half(v[j].x), __float2half(v[j].y));
        ((__half2*)g_w)[i2 + 1] = __half2(__float2half(v[j].z), __float2half(v[j].w));
    }
}

// ---------------------------------------------------------------------------
// cbT: transpose codebooks [b][d][w] -> [b][w][d]. Tiled 32x32.
// ---------------------------------------------------------------------------
__global__ void cbT_kernel(const float* __restrict__ cb) {
    __shared__ float tile[32][33];
    int b = blockIdx.z;
    int d0 = blockIdx.x * 32, w0 = blockIdx.y * 32;
    int tx = threadIdx.x, ty = threadIdx.y;   // (32, 8)
    const float* src = cb + b * 65536;
    float* dst = g_cbT + b * 65536;
#pragma unroll
    for (int j = ty; j < 32; j += 8)
        tile[j][tx] = src[(d0 + j) * 256 + w0 + tx];
    __syncthreads();
#pragma unroll
    for (int j = ty; j < 32; j += 8)
        dst[(w0 + j) * 256 + d0 + tx] = tile[tx][j];
}

// ---------------------------------------------------------------------------
// bookA: xn, softmax(x@mlp)->xc, s=cbT@xc, sn; writes fp16 planes.
// ---------------------------------------------------------------------------
__global__ void bookA_kernel(const float* __restrict__ input,
                             const float* __restrict__ mlp,
                             float* __restrict__ out_xc) {
    extern __shared__ float sm[];
    float* xc_s = sm;
    float* s_s  = sm + 4096;
    float* x_s  = sm + 8208;
    __shared__ float rinv[16], rmax[16], rsum[16];

    int b = blockIdx.y, n0 = blockIdx.x * 16;
    int t = threadIdx.x, wid = t >> 5, lane = t & 31;

#pragma unroll
    for (int i = 0; i < 16; i++)
        x_s[i * 256 + t] = input[(size_t)(n0 + i) * INFEAT + b * 256 + t];
    __syncthreads();

    for (int i = wid; i < 16; i += 8) {
        float ss = 0.f;
#pragma unroll
        for (int j = 0; j < 8; j++) { float v = x_s[i * 256 + lane + 32 * j]; ss += v * v; }
#pragma unroll
        for (int o = 16; o > 0; o >>= 1) ss += __shfl_xor_sync(0xffffffffu, ss, o);
        if (!lane) rinv[i] = 1.0f / fmaxf(sqrtf(ss), 1e-12f);
    }
    __syncthreads();
#pragma unroll
    for (int i = 0; i < 16; i++) {
        float v = x_s[i * 256 + t] * rinv[i];
        g_x[(size_t)((b << 10) + (n0 + i)) * 256 + t] = __float2half(v);
    }

    float acc[16];
#pragma unroll
    for (int i = 0; i < 16; i++) acc[i] = 0.f;
    const float* mp = mlp + b * 65536 + t;
#pragma unroll 2
    for (int d = 0; d < 256; d += 4) {
        float m0 = __ldg(mp + (d + 0) * 256);
        float m1 = __ldg(mp + (d + 1) * 256);
        float m2 = __ldg(mp + (d + 2) * 256);
        float m3 = __ldg(mp + (d + 3) * 256);
#pragma unroll
        for (int i = 0; i < 16; i++) {
            float4 xv = *(const float4*)(x_s + i * 256 + d);
            acc[i] += xv.x * m0 + xv.y * m1 + xv.z * m2 + xv.w * m3;
        }
    }
    __syncthreads();
#pragma unroll
    for (int i = 0; i < 16; i++) xc_s[i * 256 + t] = acc[i];
    __syncthreads();

    for (int i = wid; i < 16; i += 8) {
        float m = -3.4e38f;
#pragma unroll
        for (int j = 0; j < 8; j++) m = fmaxf(m, xc_s[i * 256 + lane + 32 * j]);
#pragma unroll
        for (int o = 16; o > 0; o >>= 1) m = fmaxf(m, __shfl_xor_sync(0xffffffffu, m, o));
        float se = 0.f;
#pragma unroll
        for (int j = 0; j < 8; j++) se += expf(xc_s[i * 256 + lane + 32 * j] - m);
#pragma unroll
        for (int o = 16; o > 0; o >>= 1) se += __shfl_xor_sync(0xffffffffu, se, o);
        if (!lane) { rmax[i] = m; rsum[i] = 1.0f / se; }
    }
    __syncthreads();
#pragma unroll
    for (int i = 0; i < 16; i++) {
        float v = expf(acc[i] - rmax[i]) * rsum[i];
        xc_s[i * 256 + t] = v;
        out_xc[(size_t)(n0 + i) * (BOOKS * WORDS) + b * 256 + t] = v;
    }
    __syncthreads();

    // s[i][d] = sum_w cbT[w][d] * xc[i][w]  — thread t owns d=t, coalesced __ldg
    float sacc[16];
#pragma unroll
    for (int i = 0; i < 16; i++) sacc[i] = 0.f;
    const float* cp = g_cbT + b * 65536 + t;
#pragma unroll 2
    for (int w = 0; w < 256; w += 4) {
        float c0 = __ldg(cp + (w + 0) * 256);
        float c1 = __ldg(cp + (w + 1) * 256);
        float c2 = __ldg(cp + (w + 2) * 256);
        float c3 = __ldg(cp + (w + 3) * 256);
#pragma unroll
        for (int i = 0; i < 16; i++) {
            float4 a = *(const float4*)(xc_s + i * 256 + w);
            sacc[i] += a.x * c0 + a.y * c1 + a.z * c2 + a.w * c3;
        }
    }
#pragma unroll
    for (int i = 0; i < 16; i++) s_s[i * 257 + t] = sacc[i];
    __syncthreads();

    for (int i = wid; i < 16; i += 8) {
        float ss = 0.f;
#pragma unroll
        for (int j = 0; j < 8; j++) { float v = s_s[i * 257 + lane + 32 * j]; ss += v * v; }
#pragma unroll
        for (int o = 16; o > 0; o >>= 1) ss += __shfl_xor_sync(0xffffffffu, ss, o);
        if (!lane) rinv[i] = 1.0f / fmaxf(sqrtf(ss), 1e-12f);
    }
    __syncthreads();
#pragma unroll
    for (int i = 0; i < 16; i++) {
        float v = s_s[i * 257 + t] * rinv[i];
        g_s[(size_t)((b << 10) + (n0 + i)) * 256 + t] = __float2half(v);
    }
}

// ---------------------------------------------------------------------------
// Dual GEMM: single fp16 MMA per k16 (fp32 accumulate).
// 512 threads / 16 warps, warp-specialized: warps 0-7 out1(x), 8-15 out2(s).
// Block 128(n) x 128(o), BK=32, 3-stage circular cp.async pipeline.
// Stage: x s w, each [128][40] fp16 = 10240 B -> 30720 B, x3 = 92160 B.
// ---------------------------------------------------------------------------
#define TILE_B 10240
#define STAGE_B 30720

__global__ void __launch_bounds__(512, 1)
gemm_mma(const int* __restrict__ label,
         float* __restrict__ out1,
         float* __restrict__ out2) {
    extern __shared__ char smc[];
    __shared__ float winv_s[128];
    uint32_t sb = smem_u32(smc);
    int t = threadIdx.x, wid = t >> 5, lane = t & 31;
    int b = blockIdx.z, n0 = blockIdx.y * 128, o0 = blockIdx.x * 128;

    if (t < 128) winv_s[t] = g_winv[b * OUTF + o0 + t];

    const __half* px = g_x + (size_t)((b << 10) + n0) * 256;
    const __half* ps = g_s + (size_t)((b << 10) + n0) * 256;
    const __half* pw = g_w + ((size_t)b * OUTF + o0) * 256;

    int lrow = t >> 2, lseg = t & 3;
    uint32_t cpo = (uint32_t)(lrow * 80 + lseg * 16);
    int ge = lrow * 256 + lseg * 8;

#define LOAD_STAGE(chunk, buf)                                              \
    {                                                                       \
        uint32_t base_ = sb + (uint32_t)(buf) * STAGE_B;                    \
        int g_ = ge + (chunk) * 32;                                         \
        cp16(base_ + cpo,              px + g_);                            \
        cp16(base_ + TILE_B + cpo,     ps + g_);                            \
        cp16(base_ + 2 * TILE_B + cpo, pw + g_);                            \
        cp_commit();                                                        \
    }

    int wg  = wid >> 3;            // 0: x->out1, 1: s->out2
    int wl8 = wid & 7;
    int wm = wl8 & 1, wo = wl8 >> 1;
    int m0 = wm * 64, ow0 = wo * 32;
    uint32_t aoff = (uint32_t)wg * TILE_B;   // x or s plane

    float acc[4][4][4];
#pragma unroll
    for (int mt = 0; mt < 4; mt++)
#pragma unroll
        for (int ot = 0; ot < 4; ot++)
#pragma unroll
            for (int q = 0; q < 4; q++) acc[mt][ot][q] = 0.f;

    uint32_t a_row = (uint32_t)(m0 + (lane & 7) + ((lane >> 3) & 1) * 8);
    uint32_t b_row = (uint32_t)(ow0 + (lane & 7) + ((lane >> 4) & 1) * 8);

    LOAD_STAGE(0, 0)
    LOAD_STAGE(1, 1)

    int buf = 0;
    for (int i = 0; i < 8; i++) {
        if (i < 7) cp_wait1(); else cp_wait0();
        __syncthreads();
        if (i + 2 < 8) {
            int nb = buf + 2; if (nb >= 3) nb -= 3;
            LOAD_STAGE(i + 2, nb)
        }
        uint32_t base = sb + (uint32_t)buf * STAGE_B;

#pragma unroll
        for (int kk = 0; kk < 32; kk += 16) {
            uint32_t a_addr = base + a_row * 80 + (uint32_t)((kk + ((lane >> 4) & 1) * 8) * 2);
            uint32_t b_addr = base + b_row * 80 + (uint32_t)((kk + ((lane >> 3) & 1) * 8) * 2);

            uint32_t fw[2][4];               // pair p covers ot=2p, 2p+1
#pragma unroll
            for (int p = 0; p < 2; p++)
                ldm4(fw[p], b_addr + (uint32_t)(p * 16 * 80) + 2 * TILE_B);

#pragma unroll
            for (int mt = 0; mt < 4; mt++) {
                uint32_t fa[4];
                ldm4(fa, a_addr + (uint32_t)(mt * 16 * 80) + aoff);
#pragma unroll
                for (int ot = 0; ot < 4; ot++)
                    mma16816f(acc[mt][ot], fa, &fw[ot >> 1][(ot & 1) * 2]);
            }
        }
        buf++; if (buf >= 3) buf = 0;
    }

    // ---- epilogue
    float* op = wg ? out2 : out1;
#pragma unroll
    for (int mt = 0; mt < 4; mt++) {
        int r  = n0 + m0 + mt * 16 + (lane >> 2);
        int la = label[r], lb = label[r + 8];
        size_t ro  = (size_t)r * (BOOKS * OUTF) + (size_t)b * OUTF;
        size_t ro8 = ro + (size_t)8 * (BOOKS * OUTF);
#pragma unroll
        for (int ot = 0; ot < 4; ot++) {
            int oc = ow0 + ot * 8 + 2 * (lane & 3);
            int o  = o0 + oc;
            float wi0 = winv_s[oc], wi1 = winv_s[oc + 1];
            float* A = acc[mt][ot];
            float v;
            float2 u;
            v = fminf(fmaxf(A[0] * wi0, -1.f), 1.f); if (la == o)     v -= .5f; u.x = 30.f * v;
            v = fminf(fmaxf(A[1] * wi1, -1.f), 1.f); if (la == o + 1) v -= .5f; u.y = 30.f * v;
            *(float2*)(op + ro + o) = u;
            v = fminf(fmaxf(A[2] * wi0, -1.f), 1.f); if (lb == o)     v -= .5f; u.x = 30.f * v;
            v = fminf(fmaxf(A[3] * wi1, -1.f), 1.f); if (lb == o + 1) v -= .5f; u.y = 30.f * v;
            *(float2*)(op + ro8 + o) = u;
        }
    }
}

// ---------------------------------------------------------------------------
extern "C" void kernel_launch(void* const* d_in, const int* in_sizes, int n_in,
                              void* d_out, int out_size) {
    const float* input  = (const float*)d_in[0];
    const int*   label  = (const int*)d_in[1];     // int32 (JAX default x64 off)
    const float* weight = (const float*)d_in[2];
    const float* mlp    = (const float*)d_in[3];
    const float* cb     = (const float*)d_in[4];

    float* out  = (float*)d_out;
    float* out1 = out;                                    // [1024][8][4096]
    float* out2 = out + (size_t)NROWS * BOOKS * OUTF;     // [1024][8][4096]
    float* out3 = out + (size_t)2 * NROWS * BOOKS * OUTF; // [1024][8][256]

    cudaFuncSetAttribute(bookA_kernel, cudaFuncAttributeMaxDynamicSharedMemorySize, 49216);
    cudaFuncSetAttribute(gemm_mma, cudaFuncAttributeMaxDynamicSharedMemorySize, 3 * STAGE_B);

    wprep_kernel<<<(BOOKS * OUTF) / 8, 256>>>(weight);
    cbT_kernel<<<dim3(8, 8, BOOKS), dim3(32, 8)>>>(cb);
    bookA_kernel<<<dim3(NROWS / 16, BOOKS), 256, 49216>>>(input, mlp, out3);
    gemm_mma<<<dim3(OUTF / 128, NROWS / 128, BOOKS), 512, 3 * STAGE_B>>>(label, out1, out2);
}

// round 16
// speedup vs baseline: 3.2315x; 1.0693x over previous
#include <cuda_runtime.h>
#include <cuda_fp16.h>
#include <cstdint>

#define BOOKS 8
#define NROWS 1024
#define INFEAT 2048
#define OUTF 4096
#define LW 256
#define WORDS 256

// Scratch (device globals; no runtime allocation allowed)
__device__ __half g_x[BOOKS * NROWS * LW];     // fp16(xn)
__device__ __half g_s[BOOKS * NROWS * LW];     // fp16(sn)
__device__ __half g_w[BOOKS * OUTF * LW];      // fp16(weight)
__device__ float g_winv[BOOKS * OUTF];
__device__ float g_cbT[BOOKS * WORDS * LW];    // cb transposed: [b][w][d]

// ===========================================================================
// helpers
// ===========================================================================
__device__ __forceinline__ uint32_t smem_u32(const void* p) {
    uint32_t a;
    asm("{ .reg .u64 t; cvta.to.shared.u64 t, %1; cvt.u32.u64 %0, t; }" : "=r"(a) : "l"(p));
    return a;
}
__device__ __forceinline__ void cp16(uint32_t dst, const void* src) {
    asm volatile("cp.async.cg.shared.global [%0], [%1], 16;" :: "r"(dst), "l"(src));
}
__device__ __forceinline__ void cp_commit() { asm volatile("cp.async.commit_group;"); }
__device__ __forceinline__ void cp_wait1()  { asm volatile("cp.async.wait_group 1;"); }
__device__ __forceinline__ void cp_wait0()  { asm volatile("cp.async.wait_group 0;"); }

__device__ __forceinline__ void ldm4(uint32_t* r, uint32_t addr) {
    asm volatile("ldmatrix.sync.aligned.m8n8.x4.shared.b16 {%0,%1,%2,%3}, [%4];"
                 : "=r"(r[0]), "=r"(r[1]), "=r"(r[2]), "=r"(r[3]) : "r"(addr));
}
__device__ __forceinline__ void mma16816f(float* d, const uint32_t* a, const uint32_t* b) {
    asm volatile(
        "mma.sync.aligned.m16n8k16.row.col.f32.f16.f16.f32 "
        "{%0,%1,%2,%3}, {%4,%5,%6,%7}, {%8,%9}, {%0,%1,%2,%3};"
        : "+f"(d[0]), "+f"(d[1]), "+f"(d[2]), "+f"(d[3])
        : "r"(a[0]), "r"(a[1]), "r"(a[2]), "r"(a[3]), "r"(b[0]), "r"(b[1]));
}

// ---------------------------------------------------------------------------
// wprep: winv + fp16 weight plane, single pass. 1 warp per row.
// ---------------------------------------------------------------------------
__global__ void wprep_kernel(const float* __restrict__ weight) {
    int row  = blockIdx.x * 8 + (threadIdx.x >> 5);
    int lane = threadIdx.x & 31;
    const float4* w4 = (const float4*)(weight + (size_t)row * LW);
    float ss = 0.f;
    float4 v[2];
#pragma unroll
    for (int j = 0; j < 2; j++) {
        v[j] = w4[lane + 32 * j];
        ss += v[j].x * v[j].x + v[j].y * v[j].y + v[j].z * v[j].z + v[j].w * v[j].w;
    }
#pragma unroll
    for (int o = 16; o > 0; o >>= 1) ss += __shfl_xor_sync(0xffffffffu, ss, o);
    if (lane == 0) g_winv[row] = 1.0f / fmaxf(sqrtf(ss), 1e-12f);
#pragma unroll
    for (int j = 0; j < 2; j++) {
        size_t i2 = (size_t)row * (LW / 2) + (lane + 32 * j) * 2;
        ((__half2*)g_w)[i2]     = __half2(__float2half(v[j].x), __float2half(v[j].y));
        ((__half2*)g_w)[i2 + 1] = __half2(__float2half(v[j].z), __float2half(v[j].w));
    }
}

// ---------------------------------------------------------------------------
// cbT: transpose codebooks [b][d][w] -> [b][w][d]. Tiled 32x32.
// ---------------------------------------------------------------------------
__global__ void cbT_kernel(const float* __restrict__ cb) {
    __shared__ float tile[32][33];
    int b = blockIdx.z;
    int d0 = blockIdx.x * 32, w0 = blockIdx.y * 32;
    int tx = threadIdx.x, ty = threadIdx.y;   // (32, 8)
    const float* src = cb + b * 65536;
    float* dst = g_cbT + b * 65536;
#pragma unroll
    for (int j = ty; j < 32; j += 8)
        tile[j][tx] = src[(d0 + j) * 256 + w0 + tx];
    __syncthreads();
#pragma unroll
    for (int j = ty; j < 32; j += 8)
        dst[(w0 + j) * 256 + d0 + tx] = tile[tx][j];
}

// ---------------------------------------------------------------------------
// bookA: xn, softmax(x@mlp)->xc, s=cbT@xc, sn; writes fp16 planes.
// ---------------------------------------------------------------------------
__global__ void bookA_kernel(const float* __restrict__ input,
                             const float* __restrict__ mlp,
                             float* __restrict__ out_xc) {
    extern __shared__ float sm[];
    float* xc_s = sm;
    float* s_s  = sm + 4096;
    float* x_s  = sm + 8208;
    __shared__ float rinv[16], rmax[16], rsum[16];

    int b = blockIdx.y, n0 = blockIdx.x * 16;
    int t = threadIdx.x, wid = t >> 5, lane = t & 31;

#pragma unroll
    for (int i = 0; i < 16; i++)
        x_s[i * 256 + t] = input[(size_t)(n0 + i) * INFEAT + b * 256 + t];
    __syncthreads();

    for (int i = wid; i < 16; i += 8) {
        float ss = 0.f;
#pragma unroll
        for (int j = 0; j < 8; j++) { float v = x_s[i * 256 + lane + 32 * j]; ss += v * v; }
#pragma unroll
        for (int o = 16; o > 0; o >>= 1) ss += __shfl_xor_sync(0xffffffffu, ss, o);
        if (!lane) rinv[i] = 1.0f / fmaxf(sqrtf(ss), 1e-12f);
    }
    __syncthreads();
#pragma unroll
    for (int i = 0; i < 16; i++) {
        float v = x_s[i * 256 + t] * rinv[i];
        g_x[(size_t)((b << 10) + (n0 + i)) * 256 + t] = __float2half(v);
    }

    float acc[16];
#pragma unroll
    for (int i = 0; i < 16; i++) acc[i] = 0.f;
    const float* mp = mlp + b * 65536 + t;
#pragma unroll 2
    for (int d = 0; d < 256; d += 4) {
        float m0 = __ldg(mp + (d + 0) * 256);
        float m1 = __ldg(mp + (d + 1) * 256);
        float m2 = __ldg(mp + (d + 2) * 256);
        float m3 = __ldg(mp + (d + 3) * 256);
#pragma unroll
        for (int i = 0; i < 16; i++) {
            float4 xv = *(const float4*)(x_s + i * 256 + d);
            acc[i] += xv.x * m0 + xv.y * m1 + xv.z * m2 + xv.w * m3;
        }
    }
    __syncthreads();
#pragma unroll
    for (int i = 0; i < 16; i++) xc_s[i * 256 + t] = acc[i];
    __syncthreads();

    for (int i = wid; i < 16; i += 8) {
        float m = -3.4e38f;
#pragma unroll
        for (int j = 0; j < 8; j++) m = fmaxf(m, xc_s[i * 256 + lane + 32 * j]);
#pragma unroll
        for (int o = 16; o > 0; o >>= 1) m = fmaxf(m, __shfl_xor_sync(0xffffffffu, m, o));
        float se = 0.f;
#pragma unroll
        for (int j = 0; j < 8; j++) se += expf(xc_s[i * 256 + lane + 32 * j] - m);
#pragma unroll
        for (int o = 16; o > 0; o >>= 1) se += __shfl_xor_sync(0xffffffffu, se, o);
        if (!lane) { rmax[i] = m; rsum[i] = 1.0f / se; }
    }
    __syncthreads();
#pragma unroll
    for (int i = 0; i < 16; i++) {
        float v = expf(acc[i] - rmax[i]) * rsum[i];
        xc_s[i * 256 + t] = v;
        out_xc[(size_t)(n0 + i) * (BOOKS * WORDS) + b * 256 + t] = v;
    }
    __syncthreads();

    // s[i][d] = sum_w cbT[w][d] * xc[i][w]  — thread t owns d=t, coalesced __ldg
    float sacc[16];
#pragma unroll
    for (int i = 0; i < 16; i++) sacc[i] = 0.f;
    const float* cp = g_cbT + b * 65536 + t;
#pragma unroll 2
    for (int w = 0; w < 256; w += 4) {
        float c0 = __ldg(cp + (w + 0) * 256);
        float c1 = __ldg(cp + (w + 1) * 256);
        float c2 = __ldg(cp + (w + 2) * 256);
        float c3 = __ldg(cp + (w + 3) * 256);
#pragma unroll
        for (int i = 0; i < 16; i++) {
            float4 a = *(const float4*)(xc_s + i * 256 + w);
            sacc[i] += a.x * c0 + a.y * c1 + a.z * c2 + a.w * c3;
        }
    }
#pragma unroll
    for (int i = 0; i < 16; i++) s_s[i * 257 + t] = sacc[i];
    __syncthreads();

    for (int i = wid; i < 16; i += 8) {
        float ss = 0.f;
#pragma unroll
        for (int j = 0; j < 8; j++) { float v = s_s[i * 257 + lane + 32 * j]; ss += v * v; }
#pragma unroll
        for (int o = 16; o > 0; o >>= 1) ss += __shfl_xor_sync(0xffffffffu, ss, o);
        if (!lane) rinv[i] = 1.0f / fmaxf(sqrtf(ss), 1e-12f);
    }
    __syncthreads();
#pragma unroll
    for (int i = 0; i < 16; i++) {
        float v = s_s[i * 257 + t] * rinv[i];
        g_s[(size_t)((b << 10) + (n0 + i)) * 256 + t] = __float2half(v);
    }
}

// ---------------------------------------------------------------------------
// Dual GEMM: single fp16 MMA per k16 (fp32 accumulate).
// 256 threads / 8 warps, 2 BLOCKS PER SM. Block 64(n) x 128(o), BK=32,
// 3-stage circular cp.async pipeline, warp-specialized:
// warps 0-3 out1(x), 4-7 out2(s); per-group warp grid 1(m) x 4(o),
// warp tile 64x32 (identical per-warp pattern to validated R15).
// Stage: x[64][40] 5120 + s[64][40] 5120 + w[128][40] 10240 = 20480 B, x3.
// ---------------------------------------------------------------------------
#define XS_B 5120
#define W_OFF 10240      // 2*XS_B
#define STAGE_B 20480

__global__ void __launch_bounds__(256, 2)
gemm_mma(const int* __restrict__ label,
         float* __restrict__ out1,
         float* __restrict__ out2) {
    extern __shared__ char smc[];
    __shared__ float winv_s[128];
    uint32_t sb = smem_u32(smc);
    int t = threadIdx.x, wid = t >> 5, lane = t & 31;
    int b = blockIdx.z, n0 = blockIdx.y * 64, o0 = blockIdx.x * 128;

    if (t < 128) winv_s[t] = g_winv[b * OUTF + o0 + t];

    const __half* px = g_x + (size_t)((b << 10) + n0) * 256;
    const __half* ps = g_s + (size_t)((b << 10) + n0) * 256;
    const __half* pw = g_w + ((size_t)b * OUTF + o0) * 256;

    int rowA = t >> 2, seg = t & 3;            // 256 threads -> 64 rows x 4 segs
    uint32_t cpo = (uint32_t)(rowA * 80 + seg * 16);
    int goff = rowA * 256 + seg * 8;

#define LOAD_STAGE(chunk, buf)                                              \
    {                                                                       \
        uint32_t base_ = sb + (uint32_t)(buf) * STAGE_B;                    \
        int g_ = goff + (chunk) * 32;                                       \
        cp16(base_ + cpo,                     px + g_);                     \
        cp16(base_ + XS_B + cpo,              ps + g_);                     \
        cp16(base_ + W_OFF + cpo,             pw + g_);                     \
        cp16(base_ + W_OFF + cpo + 64 * 80,   pw + g_ + 64 * 256);          \
        cp_commit();                                                        \
    }

    int wg = wid >> 2;             // 0: x->out1, 1: s->out2
    int wo = wid & 3;
    int ow0 = wo * 32;
    uint32_t aoff = (uint32_t)wg * XS_B;   // x or s plane

    float acc[4][4][4];
#pragma unroll
    for (int mt = 0; mt < 4; mt++)
#pragma unroll
        for (int ot = 0; ot < 4; ot++)
#pragma unroll
            for (int q = 0; q < 4; q++) acc[mt][ot][q] = 0.f;

    uint32_t a_row = (uint32_t)((lane & 7) + ((lane >> 3) & 1) * 8);
    uint32_t b_row = (uint32_t)(ow0 + (lane & 7) + ((lane >> 4) & 1) * 8);

    LOAD_STAGE(0, 0)
    LOAD_STAGE(1, 1)

    int buf = 0;
    for (int i = 0; i < 8; i++) {
        if (i < 7) cp_wait1(); else cp_wait0();
        __syncthreads();
        if (i + 2 < 8) {
            int nb = buf + 2; if (nb >= 3) nb -= 3;
            LOAD_STAGE(i + 2, nb)
        }
        uint32_t base = sb + (uint32_t)buf * STAGE_B;

#pragma unroll
        for (int kk = 0; kk < 32; kk += 16) {
            uint32_t a_addr = base + aoff + a_row * 80
                            + (uint32_t)((kk + ((lane >> 4) & 1) * 8) * 2);
            uint32_t b_addr = base + W_OFF + b_row * 80
                            + (uint32_t)((kk + ((lane >> 3) & 1) * 8) * 2);

            uint32_t fw[2][4];               // pair p covers ot=2p, 2p+1
#pragma unroll
            for (int p = 0; p < 2; p++)
                ldm4(fw[p], b_addr + (uint32_t)(p * 16 * 80));

#pragma unroll
            for (int mt = 0; mt < 4; mt++) {
                uint32_t fa[4];
                ldm4(fa, a_addr + (uint32_t)(mt * 16 * 80));
#pragma unroll
                for (int ot = 0; ot < 4; ot++)
                    mma16816f(acc[mt][ot], fa, &fw[ot >> 1][(ot & 1) * 2]);
            }
        }
        buf++; if (buf >= 3) buf = 0;
    }

    // ---- epilogue
    float* op = wg ? out2 : out1;
#pragma unroll
    for (int mt = 0; mt < 4; mt++) {
        int r  = n0 + mt * 16 + (lane >> 2);
        int la = label[r], lb = label[r + 8];
        size_t ro  = (size_t)r * (BOOKS * OUTF) + (size_t)b * OUTF;
        size_t ro8 = ro + (size_t)8 * (BOOKS * OUTF);
#pragma unroll
        for (int ot = 0; ot < 4; ot++) {
            int oc = ow0 + ot * 8 + 2 * (lane & 3);
            int o  = o0 + oc;
            float wi0 = winv_s[oc], wi1 = winv_s[oc + 1];
            float* A = acc[mt][ot];
            float v;
            float2 u;
            v = fminf(fmaxf(A[0] * wi0, -1.f), 1.f); if (la == o)     v -= .5f; u.x = 30.f * v;
            v = fminf(fmaxf(A[1] * wi1, -1.f), 1.f); if (la == o + 1) v -= .5f; u.y = 30.f * v;
            *(float2*)(op + ro + o) = u;
            v = fminf(fmaxf(A[2] * wi0, -1.f), 1.f); if (lb == o)     v -= .5f; u.x = 30.f * v;
            v = fminf(fmaxf(A[3] * wi1, -1.f), 1.f); if (lb == o + 1) v -= .5f; u.y = 30.f * v;
            *(float2*)(op + ro8 + o) = u;
        }
    }
}

// ---------------------------------------------------------------------------
extern "C" void kernel_launch(void* const* d_in, const int* in_sizes, int n_in,
                              void* d_out, int out_size) {
    const float* input  = (const float*)d_in[0];
    const int*   label  = (const int*)d_in[1];     // int32 (JAX default x64 off)
    const float* weight = (const float*)d_in[2];
    const float* mlp    = (const float*)d_in[3];
    const float* cb     = (const float*)d_in[4];

    float* out  = (float*)d_out;
    float* out1 = out;                                    // [1024][8][4096]
    float* out2 = out + (size_t)NROWS * BOOKS * OUTF;     // [1024][8][4096]
    float* out3 = out + (size_t)2 * NROWS * BOOKS * OUTF; // [1024][8][256]

    cudaFuncSetAttribute(bookA_kernel, cudaFuncAttributeMaxDynamicSharedMemorySize, 49216);
    cudaFuncSetAttribute(gemm_mma, cudaFuncAttributeMaxDynamicSharedMemorySize, 3 * STAGE_B);

    wprep_kernel<<<(BOOKS * OUTF) / 8, 256>>>(weight);
    cbT_kernel<<<dim3(8, 8, BOOKS), dim3(32, 8)>>>(cb);
    bookA_kernel<<<dim3(NROWS / 16, BOOKS), 256, 49216>>>(input, mlp, out3);
    gemm_mma<<<dim3(OUTF / 128, NROWS / 64, BOOKS), 256, 3 * STAGE_B>>>(label, out1, out2);
}